// round 2
// baseline (speedup 1.0000x reference)
#include <cuda_runtime.h>
#include <cuda_bf16.h>
#include <math.h>

// Problem dims
#define BB 2
#define SS 2048
#define EE 2048
#define HH 16
#define KVH 4
#define HD 128
#define GG 4              // H / KV
#define ROWS (BB * SS)    // 4096

// Scratch (no cudaMalloc allowed)
__device__ float g_Q[(size_t)ROWS * HH * HD];    // 4096 x 2048
__device__ float g_K[(size_t)ROWS * KVH * HD];   // 4096 x 512
__device__ float g_V[(size_t)ROWS * KVH * HD];   // 4096 x 512
__device__ float g_CTX[(size_t)ROWS * HH * HD];  // 4096 x 2048

// ---------------------------------------------------------------------------
// SGEMM: C[M,N] = A[M,K] @ B[K,N], all row-major, M%128==0, N%128==0, K%8==0
// 128x128 block tile, K-tile 8, 256 threads, 8x8 per-thread register tile.
// ---------------------------------------------------------------------------
__global__ __launch_bounds__(256) void sgemm128(const float* __restrict__ A,
                                                const float* __restrict__ B,
                                                float* __restrict__ C,
                                                int M, int N, int K) {
    __shared__ float As[8][128];
    __shared__ float Bs[8][128];

    const int tid = threadIdx.x;
    const int arow = tid >> 1, acol = (tid & 1) << 2;   // A: 128 rows x 8 cols
    const int brow = tid >> 5, bcol = (tid & 31) << 2;  // B: 8 rows x 128 cols
    const int ty = tid >> 4, tx = tid & 15;

    const float* Ag = A + (size_t)(blockIdx.y * 128 + arow) * K + acol;
    const float* Bg = B + (size_t)brow * N + blockIdx.x * 128 + bcol;

    float acc[8][8];
#pragma unroll
    for (int i = 0; i < 8; i++)
#pragma unroll
        for (int j = 0; j < 8; j++) acc[i][j] = 0.f;

    for (int k0 = 0; k0 < K; k0 += 8) {
        float4 av = *(const float4*)(Ag + k0);
        float4 bv = *(const float4*)(Bg + (size_t)k0 * N);
        As[acol + 0][arow] = av.x;
        As[acol + 1][arow] = av.y;
        As[acol + 2][arow] = av.z;
        As[acol + 3][arow] = av.w;
        *(float4*)(&Bs[brow][bcol]) = bv;
        __syncthreads();
#pragma unroll
        for (int k = 0; k < 8; ++k) {
            float ar[8], br[8];
            *(float4*)(ar)     = *(const float4*)(&As[k][ty * 8]);
            *(float4*)(ar + 4) = *(const float4*)(&As[k][ty * 8 + 4]);
            *(float4*)(br)     = *(const float4*)(&Bs[k][tx * 8]);
            *(float4*)(br + 4) = *(const float4*)(&Bs[k][tx * 8 + 4]);
#pragma unroll
            for (int i = 0; i < 8; i++)
#pragma unroll
                for (int j = 0; j < 8; j++) acc[i][j] += ar[i] * br[j];
        }
        __syncthreads();
    }

#pragma unroll
    for (int i = 0; i < 8; i++) {
        float* Cr = C + (size_t)(blockIdx.y * 128 + ty * 8 + i) * N +
                    blockIdx.x * 128 + tx * 8;
        *(float4*)(Cr)     = make_float4(acc[i][0], acc[i][1], acc[i][2], acc[i][3]);
        *(float4*)(Cr + 4) = make_float4(acc[i][4], acc[i][5], acc[i][6], acc[i][7]);
    }
}

// ---------------------------------------------------------------------------
// RoPE in-place on [ROWS, nheads, HD] (interleaved even/odd pairs)
// ---------------------------------------------------------------------------
__global__ void rope_kernel(float* __restrict__ data, int nheads, int total) {
    int idx = blockIdx.x * blockDim.x + threadIdx.x;
    if (idx >= total) return;
    int i = idx & 63;                    // pair index 0..63
    int h = (idx >> 6) % nheads;
    int row = idx / (nheads * 64);
    int s = row & (SS - 1);
    // freq = 10000^(-i/64) = 2^(-i * log2(10000)/64)
    float freq = exp2f(-(float)i * (13.287712379549449f / 64.0f));
    float ang = (float)s * freq;
    float sn, cs;
    sincosf(ang, &sn, &cs);
    float* p = data + ((size_t)row * nheads + h) * HD + 2 * i;
    float x1 = p[0], x2 = p[1];
    p[0] = x1 * cs - x2 * sn;
    p[1] = x1 * sn + x2 * cs;
}

// ---------------------------------------------------------------------------
// Flash attention (causal, GQA, fp32): one CTA per (q-tile 64, head, batch)
// smem: Qs[64][128], KsT[128][64] (transposed for conflict-free score loop),
//       Vs[64][128], Ps[64][64]
// ---------------------------------------------------------------------------
#define FLASH_SMEM ((8192 + 8192 + 8192 + 4096) * 4)

__global__ __launch_bounds__(256) void flash_kernel(const float* __restrict__ Q,
                                                    const float* __restrict__ K,
                                                    const float* __restrict__ V,
                                                    float* __restrict__ O) {
    extern __shared__ float sm[];
    float* Qs = sm;            // 64*128
    float* KsT = sm + 8192;    // 128*64
    float* Vs = sm + 16384;    // 64*128
    float* Ps = sm + 24576;    // 64*64

    const int qt = blockIdx.x, h = blockIdx.y, b = blockIdx.z;
    const int kvh = h >> 2;  // h / G
    const int tid = threadIdx.x;
    const int ty = tid >> 4, tx = tid & 15;
    const int r0 = ty << 2;
    const float scale = 0.08838834764831845f;  // 1/sqrt(128)

    // Load Q tile (scaled)
    {
        const float* Qg = Q + (size_t)(b * SS + qt * 64) * (HH * HD) + h * HD;
        for (int i = tid; i < 2048; i += 256) {
            int r = i >> 5, c4 = (i & 31) << 2;
            float4 v = *(const float4*)(Qg + (size_t)r * (HH * HD) + c4);
            v.x *= scale; v.y *= scale; v.z *= scale; v.w *= scale;
            *(float4*)(Qs + r * 128 + c4) = v;
        }
    }

    float m_i[4], l_i[4], acc[4][8];
#pragma unroll
    for (int i = 0; i < 4; i++) {
        m_i[i] = -INFINITY;
        l_i[i] = 0.f;
#pragma unroll
        for (int j = 0; j < 8; j++) acc[i][j] = 0.f;
    }

    for (int kt = 0; kt <= qt; kt++) {
        __syncthreads();  // protect smem reuse from previous iteration
        const float* Kg = K + (size_t)(b * SS + kt * 64) * (KVH * HD) + kvh * HD;
        const float* Vg = V + (size_t)(b * SS + kt * 64) * (KVH * HD) + kvh * HD;
        // K transposed into KsT[d][r]
        for (int i = tid; i < 2048; i += 256) {
            int r = i & 63, c4 = (i >> 6) << 2;
            float4 kv = *(const float4*)(Kg + (size_t)r * (KVH * HD) + c4);
            KsT[(c4 + 0) * 64 + r] = kv.x;
            KsT[(c4 + 1) * 64 + r] = kv.y;
            KsT[(c4 + 2) * 64 + r] = kv.z;
            KsT[(c4 + 3) * 64 + r] = kv.w;
        }
        // V row-major
        for (int i = tid; i < 2048; i += 256) {
            int r = i >> 5, c4 = (i & 31) << 2;
            *(float4*)(Vs + r * 128 + c4) =
                *(const float4*)(Vg + (size_t)r * (KVH * HD) + c4);
        }
        __syncthreads();

        // Scores: s[i][j] = (Q row r0+i) . (K row tx*4+j)
        float s[4][4];
#pragma unroll
        for (int i = 0; i < 4; i++)
#pragma unroll
            for (int j = 0; j < 4; j++) s[i][j] = 0.f;

        for (int d = 0; d < 128; d += 4) {
            float4 q[4];
#pragma unroll
            for (int i = 0; i < 4; i++)
                q[i] = *(const float4*)(Qs + (r0 + i) * 128 + d);
#pragma unroll
            for (int t = 0; t < 4; t++) {
                float4 kv = *(const float4*)(KsT + (d + t) * 64 + (tx << 2));
#pragma unroll
                for (int i = 0; i < 4; i++) {
                    float qv = ((const float*)&q[i])[t];
                    s[i][0] += qv * kv.x;
                    s[i][1] += qv * kv.y;
                    s[i][2] += qv * kv.z;
                    s[i][3] += qv * kv.w;
                }
            }
        }

        // Causal mask (only the diagonal tile needs it)
        if (kt == qt) {
            int qg = qt * 64 + r0;
            int kg = kt * 64 + (tx << 2);
#pragma unroll
            for (int i = 0; i < 4; i++)
#pragma unroll
                for (int j = 0; j < 4; j++)
                    if (kg + j > qg + i) s[i][j] = -INFINITY;
        }

        // Online softmax update
#pragma unroll
        for (int i = 0; i < 4; i++) {
            float mx = fmaxf(fmaxf(s[i][0], s[i][1]), fmaxf(s[i][2], s[i][3]));
#pragma unroll
            for (int o = 8; o > 0; o >>= 1)
                mx = fmaxf(mx, __shfl_xor_sync(0xffffffffu, mx, o, 16));
            float mnew = fmaxf(m_i[i], mx);
            float alpha = expf(m_i[i] - mnew);
            float ps = 0.f;
#pragma unroll
            for (int j = 0; j < 4; j++) {
                s[i][j] = expf(s[i][j] - mnew);
                ps += s[i][j];
            }
#pragma unroll
            for (int o = 8; o > 0; o >>= 1)
                ps += __shfl_xor_sync(0xffffffffu, ps, o, 16);
            l_i[i] = l_i[i] * alpha + ps;
            m_i[i] = mnew;
#pragma unroll
            for (int j = 0; j < 8; j++) acc[i][j] *= alpha;
            *(float4*)(Ps + (r0 + i) * 64 + (tx << 2)) =
                make_float4(s[i][0], s[i][1], s[i][2], s[i][3]);
        }
        __syncthreads();

        // O += P @ V ; thread covers rows r0..r0+3, cols tx*8..tx*8+7
        for (int k = 0; k < 64; k++) {
            float p0 = Ps[(r0 + 0) * 64 + k];
            float p1 = Ps[(r0 + 1) * 64 + k];
            float p2 = Ps[(r0 + 2) * 64 + k];
            float p3 = Ps[(r0 + 3) * 64 + k];
            float4 v0 = *(const float4*)(Vs + k * 128 + (tx << 3));
            float4 v1 = *(const float4*)(Vs + k * 128 + (tx << 3) + 4);
            acc[0][0] += p0 * v0.x; acc[0][1] += p0 * v0.y;
            acc[0][2] += p0 * v0.z; acc[0][3] += p0 * v0.w;
            acc[0][4] += p0 * v1.x; acc[0][5] += p0 * v1.y;
            acc[0][6] += p0 * v1.z; acc[0][7] += p0 * v1.w;
            acc[1][0] += p1 * v0.x; acc[1][1] += p1 * v0.y;
            acc[1][2] += p1 * v0.z; acc[1][3] += p1 * v0.w;
            acc[1][4] += p1 * v1.x; acc[1][5] += p1 * v1.y;
            acc[1][6] += p1 * v1.z; acc[1][7] += p1 * v1.w;
            acc[2][0] += p2 * v0.x; acc[2][1] += p2 * v0.y;
            acc[2][2] += p2 * v0.z; acc[2][3] += p2 * v0.w;
            acc[2][4] += p2 * v1.x; acc[2][5] += p2 * v1.y;
            acc[2][6] += p2 * v1.z; acc[2][7] += p2 * v1.w;
            acc[3][0] += p3 * v0.x; acc[3][1] += p3 * v0.y;
            acc[3][2] += p3 * v0.z; acc[3][3] += p3 * v0.w;
            acc[3][4] += p3 * v1.x; acc[3][5] += p3 * v1.y;
            acc[3][6] += p3 * v1.z; acc[3][7] += p3 * v1.w;
        }
    }

    // Epilogue: normalize and write context [B,S,H,HD]
    float* Og = O + (size_t)(b * SS + qt * 64 + r0) * (HH * HD) + h * HD + (tx << 3);
#pragma unroll
    for (int i = 0; i < 4; i++) {
        float inv = 1.0f / l_i[i];
        float4 o0 = make_float4(acc[i][0] * inv, acc[i][1] * inv,
                                acc[i][2] * inv, acc[i][3] * inv);
        float4 o1 = make_float4(acc[i][4] * inv, acc[i][5] * inv,
                                acc[i][6] * inv, acc[i][7] * inv);
        *(float4*)(Og + (size_t)i * (HH * HD)) = o0;
        *(float4*)(Og + (size_t)i * (HH * HD) + 4) = o1;
    }
}

// ---------------------------------------------------------------------------
// Launch
// ---------------------------------------------------------------------------
extern "C" void kernel_launch(void* const* d_in, const int* in_sizes, int n_in,
                              void* d_out, int out_size) {
    const float* x  = (const float*)d_in[0];
    const float* Wq = (const float*)d_in[1];
    const float* Wk = (const float*)d_in[2];
    const float* Wv = (const float*)d_in[3];
    const float* Wo = (const float*)d_in[4];
    // d_in[5] = mask (ignored; causal handled structurally)

    float *Q, *K, *V, *CTX;
    cudaGetSymbolAddress((void**)&Q, g_Q);
    cudaGetSymbolAddress((void**)&K, g_K);
    cudaGetSymbolAddress((void**)&V, g_V);
    cudaGetSymbolAddress((void**)&CTX, g_CTX);

    // Projections
    sgemm128<<<dim3(EE / 128, ROWS / 128), 256>>>(x, Wq, Q, ROWS, HH * HD, EE);
    sgemm128<<<dim3((KVH * HD) / 128, ROWS / 128), 256>>>(x, Wk, K, ROWS, KVH * HD, EE);
    sgemm128<<<dim3((KVH * HD) / 128, ROWS / 128), 256>>>(x, Wv, V, ROWS, KVH * HD, EE);

    // RoPE
    rope_kernel<<<(ROWS * HH * 64) / 256, 256>>>(Q, HH, ROWS * HH * 64);
    rope_kernel<<<(ROWS * KVH * 64) / 256, 256>>>(K, KVH, ROWS * KVH * 64);

    // Flash attention
    cudaFuncSetAttribute(flash_kernel, cudaFuncAttributeMaxDynamicSharedMemorySize,
                         FLASH_SMEM);
    flash_kernel<<<dim3(SS / 64, HH, BB), 256, FLASH_SMEM>>>(Q, K, V, CTX);

    // Output projection -> d_out
    sgemm128<<<dim3(EE / 128, ROWS / 128), 256>>>(CTX, Wo, (float*)d_out,
                                                  ROWS, EE, EE);
}

// round 4
// speedup vs baseline: 1.4630x; 1.4630x over previous
#include <cuda_runtime.h>
#include <cuda_bf16.h>
#include <math.h>
#include <stdint.h>

// Problem dims
#define BB 2
#define SS 2048
#define EE 2048
#define HH 16
#define KVH 4
#define HD 128
#define ROWS (BB * SS)    // 4096

// ---------------------------------------------------------------------------
// Scratch (__device__ globals; no cudaMalloc allowed)
// ---------------------------------------------------------------------------
__device__ float g_Q[(size_t)ROWS * HH * HD];
__device__ float g_K[(size_t)ROWS * KVH * HD];
__device__ float g_V[(size_t)ROWS * KVH * HD];
__device__ float g_CTX[(size_t)ROWS * HH * HD];

__device__ __nv_bfloat16 g_Xh[(size_t)ROWS * EE];
__device__ __nv_bfloat16 g_Xl[(size_t)ROWS * EE];
__device__ __nv_bfloat16 g_CXh[(size_t)ROWS * EE];
__device__ __nv_bfloat16 g_CXl[(size_t)ROWS * EE];
__device__ __nv_bfloat16 g_Wqh[(size_t)EE * EE];   // transposed [N,K]
__device__ __nv_bfloat16 g_Wql[(size_t)EE * EE];
__device__ __nv_bfloat16 g_Wkh[(size_t)(KVH*HD) * EE];
__device__ __nv_bfloat16 g_Wkl[(size_t)(KVH*HD) * EE];
__device__ __nv_bfloat16 g_Wvh[(size_t)(KVH*HD) * EE];
__device__ __nv_bfloat16 g_Wvl[(size_t)(KVH*HD) * EE];
__device__ __nv_bfloat16 g_Woh[(size_t)EE * EE];
__device__ __nv_bfloat16 g_Wol[(size_t)EE * EE];

// ---------------------------------------------------------------------------
// Warp MMA helpers (sm_80+ HMMA path; compiles on base sm_103 target)
// ---------------------------------------------------------------------------
__device__ __forceinline__ uint32_t smem_u32(const void* p) {
    uint32_t a;
    asm("{ .reg .u64 t; cvta.to.shared.u64 t, %1; cvt.u32.u64 %0, t; }"
        : "=r"(a) : "l"(p));
    return a;
}

__device__ __forceinline__ void ldsm_x4(uint32_t* r, uint32_t addr) {
    asm volatile("ldmatrix.sync.aligned.m8n8.x4.shared.b16 {%0,%1,%2,%3}, [%4];"
                 : "=r"(r[0]), "=r"(r[1]), "=r"(r[2]), "=r"(r[3]) : "r"(addr));
}

__device__ __forceinline__ void mma16816(float* c, const uint32_t* a,
                                         uint32_t b0, uint32_t b1) {
    asm volatile(
        "mma.sync.aligned.m16n8k16.row.col.f32.bf16.bf16.f32 "
        "{%0,%1,%2,%3}, {%4,%5,%6,%7}, {%8,%9}, {%0,%1,%2,%3};"
        : "+f"(c[0]), "+f"(c[1]), "+f"(c[2]), "+f"(c[3])
        : "r"(a[0]), "r"(a[1]), "r"(a[2]), "r"(a[3]), "r"(b0), "r"(b1));
}

// ---------------------------------------------------------------------------
// fp32 -> (hi, lo) bf16 split, elementwise (vectorized x4)
// ---------------------------------------------------------------------------
__global__ __launch_bounds__(256) void split_kernel(const float* __restrict__ in,
                                                    __nv_bfloat16* __restrict__ hi,
                                                    __nv_bfloat16* __restrict__ lo,
                                                    int n4) {
    int i = blockIdx.x * blockDim.x + threadIdx.x;
    if (i >= n4) return;
    float4 v = ((const float4*)in)[i];
    __nv_bfloat16 h0 = __float2bfloat16(v.x), h1 = __float2bfloat16(v.y);
    __nv_bfloat16 h2 = __float2bfloat16(v.z), h3 = __float2bfloat16(v.w);
    __nv_bfloat16 l0 = __float2bfloat16(v.x - __bfloat162float(h0));
    __nv_bfloat16 l1 = __float2bfloat16(v.y - __bfloat162float(h1));
    __nv_bfloat16 l2 = __float2bfloat16(v.z - __bfloat162float(h2));
    __nv_bfloat16 l3 = __float2bfloat16(v.w - __bfloat162float(h3));
    ((__nv_bfloat162*)hi)[i * 2 + 0] = __nv_bfloat162(h0, h1);
    ((__nv_bfloat162*)hi)[i * 2 + 1] = __nv_bfloat162(h2, h3);
    ((__nv_bfloat162*)lo)[i * 2 + 0] = __nv_bfloat162(l0, l1);
    ((__nv_bfloat162*)lo)[i * 2 + 1] = __nv_bfloat162(l2, l3);
}

// ---------------------------------------------------------------------------
// Transpose + split: in fp32 [Kd, Nd] -> out bf16 [Nd, Kd] (hi, lo)
// ---------------------------------------------------------------------------
__global__ __launch_bounds__(256) void tsplit_kernel(const float* __restrict__ in,
                                                     __nv_bfloat16* __restrict__ oh,
                                                     __nv_bfloat16* __restrict__ ol,
                                                     int Kd, int Nd) {
    __shared__ float t[32][33];
    int n0 = blockIdx.x * 32, k0 = blockIdx.y * 32;
    int tx = threadIdx.x & 31, ty = threadIdx.x >> 5;  // 32 x 8
#pragma unroll
    for (int j = 0; j < 4; j++)
        t[ty + j * 8][tx] = in[(size_t)(k0 + ty + j * 8) * Nd + n0 + tx];
    __syncthreads();
#pragma unroll
    for (int j = 0; j < 4; j++) {
        float v = t[tx][ty + j * 8];
        __nv_bfloat16 h = __float2bfloat16(v);
        __nv_bfloat16 l = __float2bfloat16(v - __bfloat162float(h));
        size_t o = (size_t)(n0 + ty + j * 8) * Kd + k0 + tx;
        oh[o] = h;
        ol[o] = l;
    }
}

// ---------------------------------------------------------------------------
// HMMA bf16 split-precision GEMM:
//   C[M,N] = (Ah+Al)[M,K] @ (Bh+Bl)^T, B stored [N,K] (K-major)
// 128x128 block tile, BK=32, 256 threads (8 warps, 2x4), warp tile 64x32.
// 3 MMA passes (hh, hl, lh), fp32 accumulators.
// ---------------------------------------------------------------------------
#define PAD 8
#define LDS_ROW (32 + PAD)   // bf16 elements per smem row (80 bytes)

__global__ __launch_bounds__(256) void gemm_mma(const __nv_bfloat16* __restrict__ Ah,
                                                const __nv_bfloat16* __restrict__ Al,
                                                const __nv_bfloat16* __restrict__ Bh,
                                                const __nv_bfloat16* __restrict__ Bl,
                                                float* __restrict__ C,
                                                int M, int N, int K) {
    __shared__ __nv_bfloat16 sAh[128 * LDS_ROW];
    __shared__ __nv_bfloat16 sAl[128 * LDS_ROW];
    __shared__ __nv_bfloat16 sBh[128 * LDS_ROW];
    __shared__ __nv_bfloat16 sBl[128 * LDS_ROW];

    const int tid = threadIdx.x, wid = tid >> 5, lane = tid & 31;
    const int m0 = blockIdx.y * 128, n0 = blockIdx.x * 128;
    const int warp_m = (wid >> 2) * 64;   // 0 or 64
    const int warp_n = (wid & 3) * 32;    // 0, 32, 64, 96

    const uint32_t uAh = smem_u32(sAh), uAl = smem_u32(sAl);
    const uint32_t uBh = smem_u32(sBh), uBl = smem_u32(sBl);

    // ldmatrix per-lane address offsets
    const int a_roff = ((lane >> 3) & 1) * 8 + (lane & 7);  // row within m16 tile
    const int a_coff = (lane >> 4) * 8;                     // col within k16
    const int b_roff = (lane >> 4) * 8 + (lane & 7);        // n within n16 pair
    const int b_coff = ((lane >> 3) & 1) * 8;               // k within k16

    float acc[4][4][4];
#pragma unroll
    for (int i = 0; i < 4; i++)
#pragma unroll
        for (int j = 0; j < 4; j++)
#pragma unroll
            for (int c = 0; c < 4; c++) acc[i][j][c] = 0.f;

    const __nv_bfloat16* gAh = Ah + (size_t)m0 * K;
    const __nv_bfloat16* gAl = Al + (size_t)m0 * K;
    const __nv_bfloat16* gBh = Bh + (size_t)n0 * K;
    const __nv_bfloat16* gBl = Bl + (size_t)n0 * K;

    for (int k0 = 0; k0 < K; k0 += 32) {
        __syncthreads();
        // Load 128x32 of each of the 4 arrays (each thread: 2 uint4 per array)
#pragma unroll
        for (int t = 0; t < 2; t++) {
            int idx = tid + t * 256;        // 0..511
            int r = idx >> 2, c8 = (idx & 3) * 8;
            size_t go = (size_t)r * K + k0 + c8;
            int so = r * LDS_ROW + c8;
            *(uint4*)(sAh + so) = *(const uint4*)(gAh + go);
            *(uint4*)(sAl + so) = *(const uint4*)(gAl + go);
            *(uint4*)(sBh + so) = *(const uint4*)(gBh + go);
            *(uint4*)(sBl + so) = *(const uint4*)(gBl + go);
        }
        __syncthreads();

#pragma unroll
        for (int ks = 0; ks < 2; ks++) {
            uint32_t ah[4][4], al[4][4], bh[2][4], bl[2][4];
#pragma unroll
            for (int mt = 0; mt < 4; mt++) {
                uint32_t off =
                    (uint32_t)((warp_m + mt * 16 + a_roff) * LDS_ROW +
                               ks * 16 + a_coff) * 2;
                ldsm_x4(ah[mt], uAh + off);
                ldsm_x4(al[mt], uAl + off);
            }
#pragma unroll
            for (int p = 0; p < 2; p++) {
                uint32_t off =
                    (uint32_t)((warp_n + p * 16 + b_roff) * LDS_ROW +
                               ks * 16 + b_coff) * 2;
                ldsm_x4(bh[p], uBh + off);
                ldsm_x4(bl[p], uBl + off);
            }
#pragma unroll
            for (int mt = 0; mt < 4; mt++) {
#pragma unroll
                for (int p = 0; p < 2; p++) {
#pragma unroll
                    for (int hf = 0; hf < 2; hf++) {
                        float* c = acc[mt][p * 2 + hf];
                        uint32_t b0h = bh[p][hf * 2], b1h = bh[p][hf * 2 + 1];
                        uint32_t b0l = bl[p][hf * 2], b1l = bl[p][hf * 2 + 1];
                        mma16816(c, ah[mt], b0h, b1h);   // hh
                        mma16816(c, ah[mt], b0l, b1l);   // hl
                        mma16816(c, al[mt], b0h, b1h);   // lh
                    }
                }
            }
        }
    }

    // Epilogue
    const int cr = lane >> 2, cc = (lane & 3) * 2;
#pragma unroll
    for (int mt = 0; mt < 4; mt++) {
#pragma unroll
        for (int nt = 0; nt < 4; nt++) {
            int row = m0 + warp_m + mt * 16 + cr;
            int col = n0 + warp_n + nt * 8 + cc;
            float* c = acc[mt][nt];
            *(float2*)(C + (size_t)row * N + col) = make_float2(c[0], c[1]);
            *(float2*)(C + (size_t)(row + 8) * N + col) = make_float2(c[2], c[3]);
        }
    }
}

// ---------------------------------------------------------------------------
// RoPE in-place on [ROWS, nheads, HD] (interleaved even/odd pairs)
// ---------------------------------------------------------------------------
__global__ void rope_kernel(float* __restrict__ data, int nheads, int total) {
    int idx = blockIdx.x * blockDim.x + threadIdx.x;
    if (idx >= total) return;
    int i = idx & 63;
    int h = (idx >> 6) % nheads;
    int row = idx / (nheads * 64);
    int s = row & (SS - 1);
    float freq = exp2f(-(float)i * (13.287712379549449f / 64.0f));
    float ang = (float)s * freq;
    float sn, cs;
    sincosf(ang, &sn, &cs);
    float* p = data + ((size_t)row * nheads + h) * HD + 2 * i;
    float x1 = p[0], x2 = p[1];
    p[0] = x1 * cs - x2 * sn;
    p[1] = x1 * sn + x2 * cs;
}

// ---------------------------------------------------------------------------
// Flash attention (causal, GQA, fp32): one CTA per (q-tile 64, head, batch)
// ---------------------------------------------------------------------------
#define FLASH_SMEM ((8192 + 8192 + 8192 + 4096) * 4)

__global__ __launch_bounds__(256) void flash_kernel(const float* __restrict__ Q,
                                                    const float* __restrict__ K,
                                                    const float* __restrict__ V,
                                                    float* __restrict__ O) {
    extern __shared__ float smf[];
    float* Qs = smf;
    float* KsT = smf + 8192;
    float* Vs = smf + 16384;
    float* Ps = smf + 24576;

    const int qt = blockIdx.x, h = blockIdx.y, b = blockIdx.z;
    const int kvh = h >> 2;
    const int tid = threadIdx.x;
    const int ty = tid >> 4, tx = tid & 15;
    const int r0 = ty << 2;
    const float scale = 0.08838834764831845f;

    {
        const float* Qg = Q + (size_t)(b * SS + qt * 64) * (HH * HD) + h * HD;
        for (int i = tid; i < 2048; i += 256) {
            int r = i >> 5, c4 = (i & 31) << 2;
            float4 v = *(const float4*)(Qg + (size_t)r * (HH * HD) + c4);
            v.x *= scale; v.y *= scale; v.z *= scale; v.w *= scale;
            *(float4*)(Qs + r * 128 + c4) = v;
        }
    }

    float m_i[4], l_i[4], acc[4][8];
#pragma unroll
    for (int i = 0; i < 4; i++) {
        m_i[i] = -INFINITY;
        l_i[i] = 0.f;
#pragma unroll
        for (int j = 0; j < 8; j++) acc[i][j] = 0.f;
    }

    for (int kt = 0; kt <= qt; kt++) {
        __syncthreads();
        const float* Kg = K + (size_t)(b * SS + kt * 64) * (KVH * HD) + kvh * HD;
        const float* Vg = V + (size_t)(b * SS + kt * 64) * (KVH * HD) + kvh * HD;
        for (int i = tid; i < 2048; i += 256) {
            int r = i & 63, c4 = (i >> 6) << 2;
            float4 kv = *(const float4*)(Kg + (size_t)r * (KVH * HD) + c4);
            KsT[(c4 + 0) * 64 + r] = kv.x;
            KsT[(c4 + 1) * 64 + r] = kv.y;
            KsT[(c4 + 2) * 64 + r] = kv.z;
            KsT[(c4 + 3) * 64 + r] = kv.w;
        }
        for (int i = tid; i < 2048; i += 256) {
            int r = i >> 5, c4 = (i & 31) << 2;
            *(float4*)(Vs + r * 128 + c4) =
                *(const float4*)(Vg + (size_t)r * (KVH * HD) + c4);
        }
        __syncthreads();

        float s[4][4];
#pragma unroll
        for (int i = 0; i < 4; i++)
#pragma unroll
            for (int j = 0; j < 4; j++) s[i][j] = 0.f;

        for (int d = 0; d < 128; d += 4) {
            float4 q[4];
#pragma unroll
            for (int i = 0; i < 4; i++)
                q[i] = *(const float4*)(Qs + (r0 + i) * 128 + d);
#pragma unroll
            for (int t = 0; t < 4; t++) {
                float4 kv = *(const float4*)(KsT + (d + t) * 64 + (tx << 2));
#pragma unroll
                for (int i = 0; i < 4; i++) {
                    float qv = ((const float*)&q[i])[t];
                    s[i][0] += qv * kv.x;
                    s[i][1] += qv * kv.y;
                    s[i][2] += qv * kv.z;
                    s[i][3] += qv * kv.w;
                }
            }
        }

        if (kt == qt) {
            int qg = qt * 64 + r0;
            int kg = kt * 64 + (tx << 2);
#pragma unroll
            for (int i = 0; i < 4; i++)
#pragma unroll
                for (int j = 0; j < 4; j++)
                    if (kg + j > qg + i) s[i][j] = -INFINITY;
        }

#pragma unroll
        for (int i = 0; i < 4; i++) {
            float mx = fmaxf(fmaxf(s[i][0], s[i][1]), fmaxf(s[i][2], s[i][3]));
#pragma unroll
            for (int o = 8; o > 0; o >>= 1)
                mx = fmaxf(mx, __shfl_xor_sync(0xffffffffu, mx, o, 16));
            float mnew = fmaxf(m_i[i], mx);
            float alpha = expf(m_i[i] - mnew);
            float ps = 0.f;
#pragma unroll
            for (int j = 0; j < 4; j++) {
                s[i][j] = expf(s[i][j] - mnew);
                ps += s[i][j];
            }
#pragma unroll
            for (int o = 8; o > 0; o >>= 1)
                ps += __shfl_xor_sync(0xffffffffu, ps, o, 16);
            l_i[i] = l_i[i] * alpha + ps;
            m_i[i] = mnew;
#pragma unroll
            for (int j = 0; j < 8; j++) acc[i][j] *= alpha;
            *(float4*)(Ps + (r0 + i) * 64 + (tx << 2)) =
                make_float4(s[i][0], s[i][1], s[i][2], s[i][3]);
        }
        __syncthreads();

        for (int k = 0; k < 64; k++) {
            float p0 = Ps[(r0 + 0) * 64 + k];
            float p1 = Ps[(r0 + 1) * 64 + k];
            float p2 = Ps[(r0 + 2) * 64 + k];
            float p3 = Ps[(r0 + 3) * 64 + k];
            float4 v0 = *(const float4*)(Vs + k * 128 + (tx << 3));
            float4 v1 = *(const float4*)(Vs + k * 128 + (tx << 3) + 4);
            acc[0][0] += p0 * v0.x; acc[0][1] += p0 * v0.y;
            acc[0][2] += p0 * v0.z; acc[0][3] += p0 * v0.w;
            acc[0][4] += p0 * v1.x; acc[0][5] += p0 * v1.y;
            acc[0][6] += p0 * v1.z; acc[0][7] += p0 * v1.w;
            acc[1][0] += p1 * v0.x; acc[1][1] += p1 * v0.y;
            acc[1][2] += p1 * v0.z; acc[1][3] += p1 * v0.w;
            acc[1][4] += p1 * v1.x; acc[1][5] += p1 * v1.y;
            acc[1][6] += p1 * v1.z; acc[1][7] += p1 * v1.w;
            acc[2][0] += p2 * v0.x; acc[2][1] += p2 * v0.y;
            acc[2][2] += p2 * v0.z; acc[2][3] += p2 * v0.w;
            acc[2][4] += p2 * v1.x; acc[2][5] += p2 * v1.y;
            acc[2][6] += p2 * v1.z; acc[2][7] += p2 * v1.w;
            acc[3][0] += p3 * v0.x; acc[3][1] += p3 * v0.y;
            acc[3][2] += p3 * v0.z; acc[3][3] += p3 * v0.w;
            acc[3][4] += p3 * v1.x; acc[3][5] += p3 * v1.y;
            acc[3][6] += p3 * v1.z; acc[3][7] += p3 * v1.w;
        }
    }

    float* Og = O + (size_t)(b * SS + qt * 64 + r0) * (HH * HD) + h * HD + (tx << 3);
#pragma unroll
    for (int i = 0; i < 4; i++) {
        float inv = 1.0f / l_i[i];
        float4 o0 = make_float4(acc[i][0] * inv, acc[i][1] * inv,
                                acc[i][2] * inv, acc[i][3] * inv);
        float4 o1 = make_float4(acc[i][4] * inv, acc[i][5] * inv,
                                acc[i][6] * inv, acc[i][7] * inv);
        *(float4*)(Og + (size_t)i * (HH * HD)) = o0;
        *(float4*)(Og + (size_t)i * (HH * HD) + 4) = o1;
    }
}

// ---------------------------------------------------------------------------
// Launch
// ---------------------------------------------------------------------------
extern "C" void kernel_launch(void* const* d_in, const int* in_sizes, int n_in,
                              void* d_out, int out_size) {
    const float* x  = (const float*)d_in[0];
    const float* Wq = (const float*)d_in[1];
    const float* Wk = (const float*)d_in[2];
    const float* Wv = (const float*)d_in[3];
    const float* Wo = (const float*)d_in[4];

    float *Q, *K, *V, *CTX;
    cudaGetSymbolAddress((void**)&Q, g_Q);
    cudaGetSymbolAddress((void**)&K, g_K);
    cudaGetSymbolAddress((void**)&V, g_V);
    cudaGetSymbolAddress((void**)&CTX, g_CTX);
    __nv_bfloat16 *Xh, *Xl, *CXh, *CXl, *Wqh, *Wql, *Wkh, *Wkl, *Wvh, *Wvl, *Woh, *Wol;
    cudaGetSymbolAddress((void**)&Xh, g_Xh);
    cudaGetSymbolAddress((void**)&Xl, g_Xl);
    cudaGetSymbolAddress((void**)&CXh, g_CXh);
    cudaGetSymbolAddress((void**)&CXl, g_CXl);
    cudaGetSymbolAddress((void**)&Wqh, g_Wqh);
    cudaGetSymbolAddress((void**)&Wql, g_Wql);
    cudaGetSymbolAddress((void**)&Wkh, g_Wkh);
    cudaGetSymbolAddress((void**)&Wkl, g_Wkl);
    cudaGetSymbolAddress((void**)&Wvh, g_Wvh);
    cudaGetSymbolAddress((void**)&Wvl, g_Wvl);
    cudaGetSymbolAddress((void**)&Woh, g_Woh);
    cudaGetSymbolAddress((void**)&Wol, g_Wol);

    cudaFuncSetAttribute(flash_kernel, cudaFuncAttributeMaxDynamicSharedMemorySize,
                         FLASH_SMEM);

    // Split x; transpose+split weights
    split_kernel<<<(ROWS * EE / 4 + 255) / 256, 256>>>(x, Xh, Xl, ROWS * EE / 4);
    tsplit_kernel<<<dim3(EE / 32, EE / 32), 256>>>(Wq, Wqh, Wql, EE, EE);
    tsplit_kernel<<<dim3((KVH * HD) / 32, EE / 32), 256>>>(Wk, Wkh, Wkl, EE, KVH * HD);
    tsplit_kernel<<<dim3((KVH * HD) / 32, EE / 32), 256>>>(Wv, Wvh, Wvl, EE, KVH * HD);
    tsplit_kernel<<<dim3(EE / 32, EE / 32), 256>>>(Wo, Woh, Wol, EE, EE);

    // Projections on tensor cores (HMMA, 3-pass split)
    gemm_mma<<<dim3((HH * HD) / 128, ROWS / 128), 256>>>(
        Xh, Xl, Wqh, Wql, Q, ROWS, HH * HD, EE);
    gemm_mma<<<dim3((KVH * HD) / 128, ROWS / 128), 256>>>(
        Xh, Xl, Wkh, Wkl, K, ROWS, KVH * HD, EE);
    gemm_mma<<<dim3((KVH * HD) / 128, ROWS / 128), 256>>>(
        Xh, Xl, Wvh, Wvl, V, ROWS, KVH * HD, EE);

    // RoPE
    rope_kernel<<<(ROWS * HH * 64) / 256, 256>>>(Q, HH, ROWS * HH * 64);
    rope_kernel<<<(ROWS * KVH * 64) / 256, 256>>>(K, KVH, ROWS * KVH * 64);

    // Flash attention (fp32)
    flash_kernel<<<dim3(SS / 64, HH, BB), 256, FLASH_SMEM>>>(Q, K, V, CTX);

    // Output projection on tensor cores
    split_kernel<<<(ROWS * EE / 4 + 255) / 256, 256>>>(CTX, CXh, CXl, ROWS * EE / 4);
    gemm_mma<<<dim3(EE / 128, ROWS / 128), 256>>>(
        CXh, CXl, Woh, Wol, (float*)d_out, ROWS, EE, EE);
}

// round 5
// speedup vs baseline: 2.0362x; 1.3918x over previous
#include <cuda_runtime.h>
#include <cuda_bf16.h>
#include <math.h>
#include <stdint.h>

// Problem dims
#define BB 2
#define SS 2048
#define EE 2048
#define HH 16
#define KVH 4
#define HD 128
#define ROWS (BB * SS)    // 4096

// ---------------------------------------------------------------------------
// Scratch (__device__ globals; no cudaMalloc allowed)
// ---------------------------------------------------------------------------
__device__ float g_Q[(size_t)ROWS * HH * HD];
__device__ float g_K[(size_t)ROWS * KVH * HD];
__device__ float g_V[(size_t)ROWS * KVH * HD];
__device__ float g_CTX[(size_t)ROWS * HH * HD];

__device__ __nv_bfloat16 g_Xh[(size_t)ROWS * EE];   // reused as Q-hi after gemms
__device__ __nv_bfloat16 g_Xl[(size_t)ROWS * EE];   // reused as Q-lo after gemms
__device__ __nv_bfloat16 g_CXh[(size_t)ROWS * EE];
__device__ __nv_bfloat16 g_CXl[(size_t)ROWS * EE];
__device__ __nv_bfloat16 g_Wqh[(size_t)EE * EE];    // transposed [N,K]
__device__ __nv_bfloat16 g_Wql[(size_t)EE * EE];
__device__ __nv_bfloat16 g_Wkh[(size_t)(KVH*HD) * EE];
__device__ __nv_bfloat16 g_Wkl[(size_t)(KVH*HD) * EE];
__device__ __nv_bfloat16 g_Wvh[(size_t)(KVH*HD) * EE];
__device__ __nv_bfloat16 g_Wvl[(size_t)(KVH*HD) * EE];
__device__ __nv_bfloat16 g_Woh[(size_t)EE * EE];
__device__ __nv_bfloat16 g_Wol[(size_t)EE * EE];
__device__ __nv_bfloat16 g_Kbh[(size_t)ROWS * KVH * HD];
__device__ __nv_bfloat16 g_Kbl[(size_t)ROWS * KVH * HD];
__device__ __nv_bfloat16 g_Vbh[(size_t)ROWS * KVH * HD];
__device__ __nv_bfloat16 g_Vbl[(size_t)ROWS * KVH * HD];

// ---------------------------------------------------------------------------
// Warp MMA helpers (sm_80+ HMMA path; compiles on base sm_103 target)
// ---------------------------------------------------------------------------
__device__ __forceinline__ uint32_t smem_u32(const void* p) {
    uint32_t a;
    asm("{ .reg .u64 t; cvta.to.shared.u64 t, %1; cvt.u32.u64 %0, t; }"
        : "=r"(a) : "l"(p));
    return a;
}

__device__ __forceinline__ void ldsm_x4(uint32_t* r, uint32_t addr) {
    asm volatile("ldmatrix.sync.aligned.m8n8.x4.shared.b16 {%0,%1,%2,%3}, [%4];"
                 : "=r"(r[0]), "=r"(r[1]), "=r"(r[2]), "=r"(r[3]) : "r"(addr));
}

__device__ __forceinline__ void mma16816(float* c, const uint32_t* a,
                                         uint32_t b0, uint32_t b1) {
    asm volatile(
        "mma.sync.aligned.m16n8k16.row.col.f32.bf16.bf16.f32 "
        "{%0,%1,%2,%3}, {%4,%5,%6,%7}, {%8,%9}, {%0,%1,%2,%3};"
        : "+f"(c[0]), "+f"(c[1]), "+f"(c[2]), "+f"(c[3])
        : "r"(a[0]), "r"(a[1]), "r"(a[2]), "r"(a[3]), "r"(b0), "r"(b1));
}

__device__ __forceinline__ uint32_t pack_bf16(__nv_bfloat16 a, __nv_bfloat16 b) {
    __nv_bfloat162 t(a, b);
    return *(uint32_t*)&t;
}

// ---------------------------------------------------------------------------
// fp32 -> (hi, lo) bf16 split, elementwise (vectorized x4)
// ---------------------------------------------------------------------------
__global__ __launch_bounds__(256) void split_kernel(const float* __restrict__ in,
                                                    __nv_bfloat16* __restrict__ hi,
                                                    __nv_bfloat16* __restrict__ lo,
                                                    int n4) {
    int i = blockIdx.x * blockDim.x + threadIdx.x;
    if (i >= n4) return;
    float4 v = ((const float4*)in)[i];
    __nv_bfloat16 h0 = __float2bfloat16(v.x), h1 = __float2bfloat16(v.y);
    __nv_bfloat16 h2 = __float2bfloat16(v.z), h3 = __float2bfloat16(v.w);
    __nv_bfloat16 l0 = __float2bfloat16(v.x - __bfloat162float(h0));
    __nv_bfloat16 l1 = __float2bfloat16(v.y - __bfloat162float(h1));
    __nv_bfloat16 l2 = __float2bfloat16(v.z - __bfloat162float(h2));
    __nv_bfloat16 l3 = __float2bfloat16(v.w - __bfloat162float(h3));
    ((__nv_bfloat162*)hi)[i * 2 + 0] = __nv_bfloat162(h0, h1);
    ((__nv_bfloat162*)hi)[i * 2 + 1] = __nv_bfloat162(h2, h3);
    ((__nv_bfloat162*)lo)[i * 2 + 0] = __nv_bfloat162(l0, l1);
    ((__nv_bfloat162*)lo)[i * 2 + 1] = __nv_bfloat162(l2, l3);
}

// ---------------------------------------------------------------------------
// RoPE + scale + split fused: fp32 [ROWS, nh, HD] -> bf16 hi/lo same layout
// ---------------------------------------------------------------------------
__global__ __launch_bounds__(256) void rope_split_kernel(
    const float* __restrict__ in, __nv_bfloat16* __restrict__ oh,
    __nv_bfloat16* __restrict__ ol, int nheads, float scale, int total4) {
    int idx = blockIdx.x * blockDim.x + threadIdx.x;
    if (idx >= total4) return;
    int t = idx & 31;                 // float4 slot within head row (HD/4)
    int row = idx / (32 * nheads);
    int s = row & (SS - 1);
    float4 v = ((const float4*)in)[idx];
    int i0 = t * 2, i1 = t * 2 + 1;
    float f0 = exp2f(-(float)i0 * (13.287712379549449f / 64.0f));
    float f1 = exp2f(-(float)i1 * (13.287712379549449f / 64.0f));
    float sn0, cs0, sn1, cs1;
    sincosf((float)s * f0, &sn0, &cs0);
    sincosf((float)s * f1, &sn1, &cs1);
    float y0 = (v.x * cs0 - v.y * sn0) * scale;
    float y1 = (v.x * sn0 + v.y * cs0) * scale;
    float y2 = (v.z * cs1 - v.w * sn1) * scale;
    float y3 = (v.z * sn1 + v.w * cs1) * scale;
    __nv_bfloat16 h0 = __float2bfloat16(y0), h1 = __float2bfloat16(y1);
    __nv_bfloat16 h2 = __float2bfloat16(y2), h3 = __float2bfloat16(y3);
    __nv_bfloat16 l0 = __float2bfloat16(y0 - __bfloat162float(h0));
    __nv_bfloat16 l1 = __float2bfloat16(y1 - __bfloat162float(h1));
    __nv_bfloat16 l2 = __float2bfloat16(y2 - __bfloat162float(h2));
    __nv_bfloat16 l3 = __float2bfloat16(y3 - __bfloat162float(h3));
    ((__nv_bfloat162*)oh)[idx * 2 + 0] = __nv_bfloat162(h0, h1);
    ((__nv_bfloat162*)oh)[idx * 2 + 1] = __nv_bfloat162(h2, h3);
    ((__nv_bfloat162*)ol)[idx * 2 + 0] = __nv_bfloat162(l0, l1);
    ((__nv_bfloat162*)ol)[idx * 2 + 1] = __nv_bfloat162(l2, l3);
}

// ---------------------------------------------------------------------------
// Transpose + split: in fp32 [Kd, Nd] -> out bf16 [Nd, Kd] (hi, lo)
// ---------------------------------------------------------------------------
__global__ __launch_bounds__(256) void tsplit_kernel(const float* __restrict__ in,
                                                     __nv_bfloat16* __restrict__ oh,
                                                     __nv_bfloat16* __restrict__ ol,
                                                     int Kd, int Nd) {
    __shared__ float t[32][33];
    int n0 = blockIdx.x * 32, k0 = blockIdx.y * 32;
    int tx = threadIdx.x & 31, ty = threadIdx.x >> 5;  // 32 x 8
#pragma unroll
    for (int j = 0; j < 4; j++)
        t[ty + j * 8][tx] = in[(size_t)(k0 + ty + j * 8) * Nd + n0 + tx];
    __syncthreads();
#pragma unroll
    for (int j = 0; j < 4; j++) {
        float v = t[tx][ty + j * 8];
        __nv_bfloat16 h = __float2bfloat16(v);
        __nv_bfloat16 l = __float2bfloat16(v - __bfloat162float(h));
        size_t o = (size_t)(n0 + ty + j * 8) * Kd + k0 + tx;
        oh[o] = h;
        ol[o] = l;
    }
}

// ---------------------------------------------------------------------------
// HMMA bf16 split-precision GEMM (unchanged from R3; passed @ 2.3e-5)
// ---------------------------------------------------------------------------
#define PAD 8
#define LDS_ROW (32 + PAD)

__global__ __launch_bounds__(256) void gemm_mma(const __nv_bfloat16* __restrict__ Ah,
                                                const __nv_bfloat16* __restrict__ Al,
                                                const __nv_bfloat16* __restrict__ Bh,
                                                const __nv_bfloat16* __restrict__ Bl,
                                                float* __restrict__ C,
                                                int M, int N, int K) {
    __shared__ __nv_bfloat16 sAh[128 * LDS_ROW];
    __shared__ __nv_bfloat16 sAl[128 * LDS_ROW];
    __shared__ __nv_bfloat16 sBh[128 * LDS_ROW];
    __shared__ __nv_bfloat16 sBl[128 * LDS_ROW];

    const int tid = threadIdx.x, wid = tid >> 5, lane = tid & 31;
    const int m0 = blockIdx.y * 128, n0 = blockIdx.x * 128;
    const int warp_m = (wid >> 2) * 64;
    const int warp_n = (wid & 3) * 32;

    const uint32_t uAh = smem_u32(sAh), uAl = smem_u32(sAl);
    const uint32_t uBh = smem_u32(sBh), uBl = smem_u32(sBl);

    const int a_roff = ((lane >> 3) & 1) * 8 + (lane & 7);
    const int a_coff = (lane >> 4) * 8;
    const int b_roff = (lane >> 4) * 8 + (lane & 7);
    const int b_coff = ((lane >> 3) & 1) * 8;

    float acc[4][4][4];
#pragma unroll
    for (int i = 0; i < 4; i++)
#pragma unroll
        for (int j = 0; j < 4; j++)
#pragma unroll
            for (int c = 0; c < 4; c++) acc[i][j][c] = 0.f;

    const __nv_bfloat16* gAh = Ah + (size_t)m0 * K;
    const __nv_bfloat16* gAl = Al + (size_t)m0 * K;
    const __nv_bfloat16* gBh = Bh + (size_t)n0 * K;
    const __nv_bfloat16* gBl = Bl + (size_t)n0 * K;

    for (int k0 = 0; k0 < K; k0 += 32) {
        __syncthreads();
#pragma unroll
        for (int t = 0; t < 2; t++) {
            int idx = tid + t * 256;
            int r = idx >> 2, c8 = (idx & 3) * 8;
            size_t go = (size_t)r * K + k0 + c8;
            int so = r * LDS_ROW + c8;
            *(uint4*)(sAh + so) = *(const uint4*)(gAh + go);
            *(uint4*)(sAl + so) = *(const uint4*)(gAl + go);
            *(uint4*)(sBh + so) = *(const uint4*)(gBh + go);
            *(uint4*)(sBl + so) = *(const uint4*)(gBl + go);
        }
        __syncthreads();

#pragma unroll
        for (int ks = 0; ks < 2; ks++) {
            uint32_t ah[4][4], al[4][4], bh[2][4], bl[2][4];
#pragma unroll
            for (int mt = 0; mt < 4; mt++) {
                uint32_t off =
                    (uint32_t)((warp_m + mt * 16 + a_roff) * LDS_ROW +
                               ks * 16 + a_coff) * 2;
                ldsm_x4(ah[mt], uAh + off);
                ldsm_x4(al[mt], uAl + off);
            }
#pragma unroll
            for (int p = 0; p < 2; p++) {
                uint32_t off =
                    (uint32_t)((warp_n + p * 16 + b_roff) * LDS_ROW +
                               ks * 16 + b_coff) * 2;
                ldsm_x4(bh[p], uBh + off);
                ldsm_x4(bl[p], uBl + off);
            }
#pragma unroll
            for (int mt = 0; mt < 4; mt++) {
#pragma unroll
                for (int p = 0; p < 2; p++) {
#pragma unroll
                    for (int hf = 0; hf < 2; hf++) {
                        float* c = acc[mt][p * 2 + hf];
                        uint32_t b0h = bh[p][hf * 2], b1h = bh[p][hf * 2 + 1];
                        uint32_t b0l = bl[p][hf * 2], b1l = bl[p][hf * 2 + 1];
                        mma16816(c, ah[mt], b0h, b1h);
                        mma16816(c, ah[mt], b0l, b1l);
                        mma16816(c, al[mt], b0h, b1h);
                    }
                }
            }
        }
    }

    const int cr = lane >> 2, cc = (lane & 3) * 2;
#pragma unroll
    for (int mt = 0; mt < 4; mt++) {
#pragma unroll
        for (int nt = 0; nt < 4; nt++) {
            int row = m0 + warp_m + mt * 16 + cr;
            int col = n0 + warp_n + nt * 8 + cc;
            float* c = acc[mt][nt];
            *(float2*)(C + (size_t)row * N + col) = make_float2(c[0], c[1]);
            *(float2*)(C + (size_t)(row + 8) * N + col) = make_float2(c[2], c[3]);
        }
    }
}

// ---------------------------------------------------------------------------
// Flash attention on HMMA (causal, GQA, 3-pass hi/lo split)
// BQ=128 (8 warps x 16 rows), BK=64, HD=128. P kept in registers.
// smem bf16: Qh[128][136] Ql[128][136] Kh[64][136] Kl[64][136]
//            Vth[128][72] Vtl[128][72]  (V transposed)
// ---------------------------------------------------------------------------
#define FLA_SMEM 141312

__global__ __launch_bounds__(256) void flash_mma(
    const __nv_bfloat16* __restrict__ Qh, const __nv_bfloat16* __restrict__ Ql,
    const __nv_bfloat16* __restrict__ Kh, const __nv_bfloat16* __restrict__ Kl,
    const __nv_bfloat16* __restrict__ Vh, const __nv_bfloat16* __restrict__ Vl,
    float* __restrict__ O) {
    extern __shared__ __nv_bfloat16 sb[];
    __nv_bfloat16* sQh  = sb;            // [128][136]
    __nv_bfloat16* sQl  = sb + 17408;
    __nv_bfloat16* sKh  = sb + 34816;    // [64][136]
    __nv_bfloat16* sKl  = sb + 43520;
    __nv_bfloat16* sVth = sb + 52224;    // [128][72]
    __nv_bfloat16* sVtl = sb + 61440;

    const int qt = gridDim.x - 1 - blockIdx.x;   // heavy tiles first
    const int h = blockIdx.y, b = blockIdx.z;
    const int kvh = h >> 2;
    const int tid = threadIdx.x, wid = tid >> 5, lane = tid & 31;
    const int cr = lane >> 2, tc = (lane & 3) << 1;

    const int a_roff = ((lane >> 3) & 1) * 8 + (lane & 7);
    const int a_coff = (lane >> 4) * 8;
    const int b_roff = (lane >> 4) * 8 + (lane & 7);
    const int b_coff = ((lane >> 3) & 1) * 8;

    // Load Q tile (bf16 hi/lo, scale already folded in)
    {
        const size_t qbase = ((size_t)(b * SS + qt * 128) * HH + h) * HD;
        for (int i = tid; i < 2048; i += 256) {
            int r = i >> 4, c8 = (i & 15) << 3;
            size_t g = qbase + (size_t)r * (HH * HD) + c8;
            *(uint4*)(sQh + r * 136 + c8) = *(const uint4*)(Qh + g);
            *(uint4*)(sQl + r * 136 + c8) = *(const uint4*)(Ql + g);
        }
    }
    __syncthreads();

    const uint32_t uQh = smem_u32(sQh), uQl = smem_u32(sQl);
    const uint32_t uKh = smem_u32(sKh), uKl = smem_u32(sKl);
    const uint32_t uVh = smem_u32(sVth), uVl = smem_u32(sVtl);

    // Hoist Q-hi fragments (Q fixed for whole CTA)
    uint32_t qh[8][4];
#pragma unroll
    for (int ks = 0; ks < 8; ks++)
        ldsm_x4(qh[ks],
                uQh + (uint32_t)((wid * 16 + a_roff) * 136 + ks * 16 + a_coff) * 2);

    float oacc[16][4];
#pragma unroll
    for (int i = 0; i < 16; i++)
#pragma unroll
        for (int c = 0; c < 4; c++) oacc[i][c] = 0.f;
    float m0 = -1e30f, m1 = -1e30f, l0 = 0.f, l1 = 0.f;

    const int border = qt * 128 + wid * 16;
    const int jmax = 2 * qt + 1;

    for (int j = 0; j <= jmax; j++) {
        __syncthreads();
        // Load K tile (row-major) + V tile (transposed), hi & lo
        for (int i = tid; i < 1024; i += 256) {
            int r = i >> 4, c8 = (i & 15) << 3;
            size_t g = ((size_t)(b * SS + j * 64 + r) * KVH + kvh) * HD + c8;
            *(uint4*)(sKh + r * 136 + c8) = *(const uint4*)(Kh + g);
            *(uint4*)(sKl + r * 136 + c8) = *(const uint4*)(Kl + g);
            uint4 vh4 = *(const uint4*)(Vh + g);
            uint4 vl4 = *(const uint4*)(Vl + g);
            const __nv_bfloat16* pvh = (const __nv_bfloat16*)&vh4;
            const __nv_bfloat16* pvl = (const __nv_bfloat16*)&vl4;
#pragma unroll
            for (int e = 0; e < 8; e++) {
                sVth[(c8 + e) * 72 + r] = pvh[e];
                sVtl[(c8 + e) * 72 + r] = pvl[e];
            }
        }
        __syncthreads();

        if (j * 64 > border + 15) continue;  // tile fully above diagonal for warp

        // ---- Scores S[16x64] = Q @ K^T (3-pass split) ----
        float sacc[8][4];
#pragma unroll
        for (int nt = 0; nt < 8; nt++)
#pragma unroll
            for (int c = 0; c < 4; c++) sacc[nt][c] = 0.f;

#pragma unroll
        for (int ks = 0; ks < 8; ks++) {
            uint32_t kh4[4][4], kl4[4][4], qlf[4];
#pragma unroll
            for (int p = 0; p < 4; p++) {
                uint32_t off =
                    (uint32_t)((p * 16 + b_roff) * 136 + ks * 16 + b_coff) * 2;
                ldsm_x4(kh4[p], uKh + off);
                ldsm_x4(kl4[p], uKl + off);
            }
            ldsm_x4(qlf,
                    uQl + (uint32_t)((wid * 16 + a_roff) * 136 + ks * 16 + a_coff) * 2);
#pragma unroll
            for (int p = 0; p < 4; p++)
#pragma unroll
                for (int hf = 0; hf < 2; hf++) {
                    float* c = sacc[p * 2 + hf];
                    mma16816(c, qh[ks], kh4[p][hf * 2], kh4[p][hf * 2 + 1]);
                    mma16816(c, qh[ks], kl4[p][hf * 2], kl4[p][hf * 2 + 1]);
                    mma16816(c, qlf,    kh4[p][hf * 2], kh4[p][hf * 2 + 1]);
                }
        }

        // ---- Causal mask (diagonal tiles only) ----
        if (j * 64 + 63 > border) {
            int qg0 = border + cr, qg1 = qg0 + 8;
#pragma unroll
            for (int nt = 0; nt < 8; nt++) {
                int kg = j * 64 + nt * 8 + tc;
                if (kg > qg0) sacc[nt][0] = -1e30f;
                if (kg + 1 > qg0) sacc[nt][1] = -1e30f;
                if (kg > qg1) sacc[nt][2] = -1e30f;
                if (kg + 1 > qg1) sacc[nt][3] = -1e30f;
            }
        }

        // ---- Online softmax ----
        float mx0 = -1e30f, mx1 = -1e30f;
#pragma unroll
        for (int nt = 0; nt < 8; nt++) {
            mx0 = fmaxf(mx0, fmaxf(sacc[nt][0], sacc[nt][1]));
            mx1 = fmaxf(mx1, fmaxf(sacc[nt][2], sacc[nt][3]));
        }
        mx0 = fmaxf(mx0, __shfl_xor_sync(0xffffffffu, mx0, 1, 4));
        mx0 = fmaxf(mx0, __shfl_xor_sync(0xffffffffu, mx0, 2, 4));
        mx1 = fmaxf(mx1, __shfl_xor_sync(0xffffffffu, mx1, 1, 4));
        mx1 = fmaxf(mx1, __shfl_xor_sync(0xffffffffu, mx1, 2, 4));
        float mn0 = fmaxf(m0, mx0), mn1 = fmaxf(m1, mx1);
        float al0 = __expf(m0 - mn0), al1 = __expf(m1 - mn1);

        float sum0 = 0.f, sum1 = 0.f;
        uint32_t ph[8][2], pl[8][2];
#pragma unroll
        for (int nt = 0; nt < 8; nt++) {
            float p00 = __expf(sacc[nt][0] - mn0);
            float p01 = __expf(sacc[nt][1] - mn0);
            float p10 = __expf(sacc[nt][2] - mn1);
            float p11 = __expf(sacc[nt][3] - mn1);
            sum0 += p00 + p01;
            sum1 += p10 + p11;
            __nv_bfloat16 h0 = __float2bfloat16(p00), h1 = __float2bfloat16(p01);
            __nv_bfloat16 h2 = __float2bfloat16(p10), h3 = __float2bfloat16(p11);
            ph[nt][0] = pack_bf16(h0, h1);
            ph[nt][1] = pack_bf16(h2, h3);
            pl[nt][0] = pack_bf16(__float2bfloat16(p00 - __bfloat162float(h0)),
                                  __float2bfloat16(p01 - __bfloat162float(h1)));
            pl[nt][1] = pack_bf16(__float2bfloat16(p10 - __bfloat162float(h2)),
                                  __float2bfloat16(p11 - __bfloat162float(h3)));
        }
        sum0 += __shfl_xor_sync(0xffffffffu, sum0, 1, 4);
        sum0 += __shfl_xor_sync(0xffffffffu, sum0, 2, 4);
        sum1 += __shfl_xor_sync(0xffffffffu, sum1, 1, 4);
        sum1 += __shfl_xor_sync(0xffffffffu, sum1, 2, 4);
        l0 = l0 * al0 + sum0;
        l1 = l1 * al1 + sum1;
        m0 = mn0;
        m1 = mn1;
#pragma unroll
        for (int nt = 0; nt < 16; nt++) {
            oacc[nt][0] *= al0;
            oacc[nt][1] *= al0;
            oacc[nt][2] *= al1;
            oacc[nt][3] *= al1;
        }

        // ---- O += P @ V (3-pass split; P in regs, V^T from smem) ----
#pragma unroll
        for (int ks = 0; ks < 4; ks++) {
            uint32_t ah4[4] = {ph[2 * ks][0], ph[2 * ks][1],
                               ph[2 * ks + 1][0], ph[2 * ks + 1][1]};
            uint32_t alo[4] = {pl[2 * ks][0], pl[2 * ks][1],
                               pl[2 * ks + 1][0], pl[2 * ks + 1][1]};
#pragma unroll
            for (int p = 0; p < 8; p++) {
                uint32_t vh4[4], vl4[4];
                uint32_t off =
                    (uint32_t)((p * 16 + b_roff) * 72 + ks * 16 + b_coff) * 2;
                ldsm_x4(vh4, uVh + off);
                ldsm_x4(vl4, uVl + off);
#pragma unroll
                for (int hf = 0; hf < 2; hf++) {
                    float* c = oacc[p * 2 + hf];
                    mma16816(c, ah4, vh4[hf * 2], vh4[hf * 2 + 1]);
                    mma16816(c, ah4, vl4[hf * 2], vl4[hf * 2 + 1]);
                    mma16816(c, alo, vh4[hf * 2], vh4[hf * 2 + 1]);
                }
            }
        }
    }

    // ---- Epilogue ----
    float inv0 = 1.0f / l0, inv1 = 1.0f / l1;
    int row0 = qt * 128 + wid * 16 + cr;
    float* Ob = O + ((size_t)(b * SS + row0) * HH + h) * HD;
#pragma unroll
    for (int nt = 0; nt < 16; nt++) {
        int col = nt * 8 + tc;
        *(float2*)(Ob + col) =
            make_float2(oacc[nt][0] * inv0, oacc[nt][1] * inv0);
        *(float2*)(Ob + (size_t)8 * (HH * HD) + col) =
            make_float2(oacc[nt][2] * inv1, oacc[nt][3] * inv1);
    }
}

// ---------------------------------------------------------------------------
// Launch
// ---------------------------------------------------------------------------
extern "C" void kernel_launch(void* const* d_in, const int* in_sizes, int n_in,
                              void* d_out, int out_size) {
    const float* x  = (const float*)d_in[0];
    const float* Wq = (const float*)d_in[1];
    const float* Wk = (const float*)d_in[2];
    const float* Wv = (const float*)d_in[3];
    const float* Wo = (const float*)d_in[4];

    float *Q, *K, *V, *CTX;
    cudaGetSymbolAddress((void**)&Q, g_Q);
    cudaGetSymbolAddress((void**)&K, g_K);
    cudaGetSymbolAddress((void**)&V, g_V);
    cudaGetSymbolAddress((void**)&CTX, g_CTX);
    __nv_bfloat16 *Xh, *Xl, *CXh, *CXl, *Wqh, *Wql, *Wkh, *Wkl, *Wvh, *Wvl,
        *Woh, *Wol, *Kbh, *Kbl, *Vbh, *Vbl;
    cudaGetSymbolAddress((void**)&Xh, g_Xh);
    cudaGetSymbolAddress((void**)&Xl, g_Xl);
    cudaGetSymbolAddress((void**)&CXh, g_CXh);
    cudaGetSymbolAddress((void**)&CXl, g_CXl);
    cudaGetSymbolAddress((void**)&Wqh, g_Wqh);
    cudaGetSymbolAddress((void**)&Wql, g_Wql);
    cudaGetSymbolAddress((void**)&Wkh, g_Wkh);
    cudaGetSymbolAddress((void**)&Wkl, g_Wkl);
    cudaGetSymbolAddress((void**)&Wvh, g_Wvh);
    cudaGetSymbolAddress((void**)&Wvl, g_Wvl);
    cudaGetSymbolAddress((void**)&Woh, g_Woh);
    cudaGetSymbolAddress((void**)&Wol, g_Wol);
    cudaGetSymbolAddress((void**)&Kbh, g_Kbh);
    cudaGetSymbolAddress((void**)&Kbl, g_Kbl);
    cudaGetSymbolAddress((void**)&Vbh, g_Vbh);
    cudaGetSymbolAddress((void**)&Vbl, g_Vbl);

    cudaFuncSetAttribute(flash_mma, cudaFuncAttributeMaxDynamicSharedMemorySize,
                         FLA_SMEM);

    // Split x; transpose+split weights
    split_kernel<<<(ROWS * EE / 4 + 255) / 256, 256>>>(x, Xh, Xl, ROWS * EE / 4);
    tsplit_kernel<<<dim3(EE / 32, EE / 32), 256>>>(Wq, Wqh, Wql, EE, EE);
    tsplit_kernel<<<dim3((KVH * HD) / 32, EE / 32), 256>>>(Wk, Wkh, Wkl, EE, KVH * HD);
    tsplit_kernel<<<dim3((KVH * HD) / 32, EE / 32), 256>>>(Wv, Wvh, Wvl, EE, KVH * HD);
    tsplit_kernel<<<dim3(EE / 32, EE / 32), 256>>>(Wo, Woh, Wol, EE, EE);

    // Projections (HMMA split)
    gemm_mma<<<dim3((HH * HD) / 128, ROWS / 128), 256>>>(
        Xh, Xl, Wqh, Wql, Q, ROWS, HH * HD, EE);
    gemm_mma<<<dim3((KVH * HD) / 128, ROWS / 128), 256>>>(
        Xh, Xl, Wkh, Wkl, K, ROWS, KVH * HD, EE);
    gemm_mma<<<dim3((KVH * HD) / 128, ROWS / 128), 256>>>(
        Xh, Xl, Wvh, Wvl, V, ROWS, KVH * HD, EE);

    // RoPE + scale + bf16 split (Q reuses Xh/Xl; K/V to dedicated buffers)
    const float scale = 0.08838834764831845f;  // 1/sqrt(HD)
    rope_split_kernel<<<(ROWS * HH * 32 + 255) / 256, 256>>>(
        Q, Xh, Xl, HH, scale, ROWS * HH * 32);
    rope_split_kernel<<<(ROWS * KVH * 32 + 255) / 256, 256>>>(
        K, Kbh, Kbl, KVH, 1.0f, ROWS * KVH * 32);
    split_kernel<<<(ROWS * KVH * HD / 4 + 255) / 256, 256>>>(
        V, Vbh, Vbl, ROWS * KVH * HD / 4);

    // Flash attention on tensor cores
    flash_mma<<<dim3(SS / 128, HH, BB), 256, FLA_SMEM>>>(
        Xh, Xl, Kbh, Kbl, Vbh, Vbl, CTX);

    // Output projection (HMMA split)
    split_kernel<<<(ROWS * EE / 4 + 255) / 256, 256>>>(CTX, CXh, CXl, ROWS * EE / 4);
    gemm_mma<<<dim3(EE / 128, ROWS / 128), 256>>>(
        CXh, CXl, Woh, Wol, (float*)d_out, ROWS, EE, EE);
}

// round 6
// speedup vs baseline: 3.3748x; 1.6574x over previous
#include <cuda_runtime.h>
#include <cuda_bf16.h>
#include <math.h>
#include <stdint.h>

// Problem dims
#define BB 2
#define SS 2048
#define EE 2048
#define HH 16
#define KVH 4
#define HD 128
#define ROWS (BB * SS)    // 4096

// ---------------------------------------------------------------------------
// Scratch (__device__ globals; no cudaMalloc allowed)
// ---------------------------------------------------------------------------
__device__ float g_Q[(size_t)ROWS * HH * HD];
__device__ float g_K[(size_t)ROWS * KVH * HD];
__device__ float g_V[(size_t)ROWS * KVH * HD];
__device__ float g_CTX[(size_t)ROWS * HH * HD];

__device__ __nv_bfloat16 g_Xh[(size_t)ROWS * EE];   // reused as Q-hi after gemms
__device__ __nv_bfloat16 g_Xl[(size_t)ROWS * EE];
__device__ __nv_bfloat16 g_CXh[(size_t)ROWS * EE];
__device__ __nv_bfloat16 g_CXl[(size_t)ROWS * EE];
__device__ __nv_bfloat16 g_Wch[(size_t)(EE + 2 * KVH * HD) * EE];  // QKV concat [3072,2048]
__device__ __nv_bfloat16 g_Wcl[(size_t)(EE + 2 * KVH * HD) * EE];
__device__ __nv_bfloat16 g_Woh[(size_t)EE * EE];
__device__ __nv_bfloat16 g_Wol[(size_t)EE * EE];
__device__ __nv_bfloat16 g_Kbh[(size_t)ROWS * KVH * HD];
__device__ __nv_bfloat16 g_Kbl[(size_t)ROWS * KVH * HD];
__device__ __nv_bfloat16 g_Vbh[(size_t)ROWS * KVH * HD];
__device__ __nv_bfloat16 g_Vbl[(size_t)ROWS * KVH * HD];

// ---------------------------------------------------------------------------
// MMA / cp.async helpers
// ---------------------------------------------------------------------------
__device__ __forceinline__ uint32_t smem_u32(const void* p) {
    uint32_t a;
    asm("{ .reg .u64 t; cvta.to.shared.u64 t, %1; cvt.u32.u64 %0, t; }"
        : "=r"(a) : "l"(p));
    return a;
}
__device__ __forceinline__ void ldsm_x4(uint32_t* r, uint32_t addr) {
    asm volatile("ldmatrix.sync.aligned.m8n8.x4.shared.b16 {%0,%1,%2,%3}, [%4];"
                 : "=r"(r[0]), "=r"(r[1]), "=r"(r[2]), "=r"(r[3]) : "r"(addr));
}
__device__ __forceinline__ void ldsm_x4_t(uint32_t* r, uint32_t addr) {
    asm volatile("ldmatrix.sync.aligned.m8n8.x4.trans.shared.b16 {%0,%1,%2,%3}, [%4];"
                 : "=r"(r[0]), "=r"(r[1]), "=r"(r[2]), "=r"(r[3]) : "r"(addr));
}
__device__ __forceinline__ void mma16816(float* c, const uint32_t* a,
                                         uint32_t b0, uint32_t b1) {
    asm volatile(
        "mma.sync.aligned.m16n8k16.row.col.f32.bf16.bf16.f32 "
        "{%0,%1,%2,%3}, {%4,%5,%6,%7}, {%8,%9}, {%0,%1,%2,%3};"
        : "+f"(c[0]), "+f"(c[1]), "+f"(c[2]), "+f"(c[3])
        : "r"(a[0]), "r"(a[1]), "r"(a[2]), "r"(a[3]), "r"(b0), "r"(b1));
}
__device__ __forceinline__ void cp16(uint32_t dst, const void* src) {
    asm volatile("cp.async.cg.shared.global [%0], [%1], 16;" :: "r"(dst), "l"(src));
}
__device__ __forceinline__ void cp_commit() {
    asm volatile("cp.async.commit_group;" ::: "memory");
}
template <int N> __device__ __forceinline__ void cp_wait() {
    asm volatile("cp.async.wait_group %0;" :: "n"(N) : "memory");
}
__device__ __forceinline__ uint32_t pack_bf16(__nv_bfloat16 a, __nv_bfloat16 b) {
    __nv_bfloat162 t(a, b);
    return *(uint32_t*)&t;
}

// ---------------------------------------------------------------------------
// fp32 -> (hi, lo) bf16 split, elementwise (vectorized x4)
// ---------------------------------------------------------------------------
__global__ __launch_bounds__(256) void split_kernel(const float* __restrict__ in,
                                                    __nv_bfloat16* __restrict__ hi,
                                                    __nv_bfloat16* __restrict__ lo,
                                                    int n4) {
    int i = blockIdx.x * blockDim.x + threadIdx.x;
    if (i >= n4) return;
    float4 v = ((const float4*)in)[i];
    __nv_bfloat16 h0 = __float2bfloat16(v.x), h1 = __float2bfloat16(v.y);
    __nv_bfloat16 h2 = __float2bfloat16(v.z), h3 = __float2bfloat16(v.w);
    __nv_bfloat16 l0 = __float2bfloat16(v.x - __bfloat162float(h0));
    __nv_bfloat16 l1 = __float2bfloat16(v.y - __bfloat162float(h1));
    __nv_bfloat16 l2 = __float2bfloat16(v.z - __bfloat162float(h2));
    __nv_bfloat16 l3 = __float2bfloat16(v.w - __bfloat162float(h3));
    ((__nv_bfloat162*)hi)[i * 2 + 0] = __nv_bfloat162(h0, h1);
    ((__nv_bfloat162*)hi)[i * 2 + 1] = __nv_bfloat162(h2, h3);
    ((__nv_bfloat162*)lo)[i * 2 + 0] = __nv_bfloat162(l0, l1);
    ((__nv_bfloat162*)lo)[i * 2 + 1] = __nv_bfloat162(l2, l3);
}

// ---------------------------------------------------------------------------
// RoPE + scale + split fused: fp32 [ROWS, nh, HD] -> bf16 hi/lo same layout
// ---------------------------------------------------------------------------
__global__ __launch_bounds__(256) void rope_split_kernel(
    const float* __restrict__ in, __nv_bfloat16* __restrict__ oh,
    __nv_bfloat16* __restrict__ ol, int nheads, float scale, int total4) {
    int idx = blockIdx.x * blockDim.x + threadIdx.x;
    if (idx >= total4) return;
    int t = idx & 31;
    int row = idx / (32 * nheads);
    int s = row & (SS - 1);
    float4 v = ((const float4*)in)[idx];
    int i0 = t * 2, i1 = t * 2 + 1;
    float f0 = exp2f(-(float)i0 * (13.287712379549449f / 64.0f));
    float f1 = exp2f(-(float)i1 * (13.287712379549449f / 64.0f));
    float sn0, cs0, sn1, cs1;
    sincosf((float)s * f0, &sn0, &cs0);
    sincosf((float)s * f1, &sn1, &cs1);
    float y0 = (v.x * cs0 - v.y * sn0) * scale;
    float y1 = (v.x * sn0 + v.y * cs0) * scale;
    float y2 = (v.z * cs1 - v.w * sn1) * scale;
    float y3 = (v.z * sn1 + v.w * cs1) * scale;
    __nv_bfloat16 h0 = __float2bfloat16(y0), h1 = __float2bfloat16(y1);
    __nv_bfloat16 h2 = __float2bfloat16(y2), h3 = __float2bfloat16(y3);
    __nv_bfloat16 l0 = __float2bfloat16(y0 - __bfloat162float(h0));
    __nv_bfloat16 l1 = __float2bfloat16(y1 - __bfloat162float(h1));
    __nv_bfloat16 l2 = __float2bfloat16(y2 - __bfloat162float(h2));
    __nv_bfloat16 l3 = __float2bfloat16(y3 - __bfloat162float(h3));
    ((__nv_bfloat162*)oh)[idx * 2 + 0] = __nv_bfloat162(h0, h1);
    ((__nv_bfloat162*)oh)[idx * 2 + 1] = __nv_bfloat162(h2, h3);
    ((__nv_bfloat162*)ol)[idx * 2 + 0] = __nv_bfloat162(l0, l1);
    ((__nv_bfloat162*)ol)[idx * 2 + 1] = __nv_bfloat162(l2, l3);
}

// ---------------------------------------------------------------------------
// Transpose + split: in fp32 [Kd, Nd] -> out bf16 [Nd, Kd] (hi, lo)
// ---------------------------------------------------------------------------
__global__ __launch_bounds__(256) void tsplit_kernel(const float* __restrict__ in,
                                                     __nv_bfloat16* __restrict__ oh,
                                                     __nv_bfloat16* __restrict__ ol,
                                                     int Kd, int Nd) {
    __shared__ float t[32][33];
    int n0 = blockIdx.x * 32, k0 = blockIdx.y * 32;
    int tx = threadIdx.x & 31, ty = threadIdx.x >> 5;
#pragma unroll
    for (int j = 0; j < 4; j++)
        t[ty + j * 8][tx] = in[(size_t)(k0 + ty + j * 8) * Nd + n0 + tx];
    __syncthreads();
#pragma unroll
    for (int j = 0; j < 4; j++) {
        float v = t[tx][ty + j * 8];
        __nv_bfloat16 h = __float2bfloat16(v);
        __nv_bfloat16 l = __float2bfloat16(v - __bfloat162float(h));
        size_t o = (size_t)(n0 + ty + j * 8) * Kd + k0 + tx;
        oh[o] = h;
        ol[o] = l;
    }
}

// ---------------------------------------------------------------------------
// HMMA bf16 split-precision GEMM with cp.async double buffering.
// C routed to up to 3 outputs by column range (QKV fusion).
// ---------------------------------------------------------------------------
#define GROW 40                         // bf16 elems per smem row
#define GARR (128 * GROW * 2)           // bytes per array per stage (10240)
#define GSTAGE_B (4 * GARR)             // bytes per stage (40960)
#define GEMM_SMEM (2 * GSTAGE_B)        // 81920

#define GLOAD(kc, st)                                                        \
    do {                                                                     \
        uint32_t uS = uBase + (st) * GSTAGE_B;                               \
        int koff = (kc) * 32;                                                \
        _Pragma("unroll") for (int t = 0; t < 2; t++) {                      \
            int idx = tid + t * 256;                                         \
            int r = idx >> 2, c8 = (idx & 3) * 8;                            \
            size_t go = (size_t)r * K + koff + c8;                           \
            uint32_t dso = (uint32_t)(r * (GROW * 2) + c8 * 2);              \
            cp16(uS + dso, gAh + go);                                        \
            cp16(uS + GARR + dso, gAl + go);                                 \
            cp16(uS + 2 * GARR + dso, gBh + go);                             \
            cp16(uS + 3 * GARR + dso, gBl + go);                             \
        }                                                                    \
    } while (0)

__global__ __launch_bounds__(256) void gemm_mma(
    const __nv_bfloat16* __restrict__ Ah, const __nv_bfloat16* __restrict__ Al,
    const __nv_bfloat16* __restrict__ Bh, const __nv_bfloat16* __restrict__ Bl,
    float* __restrict__ C0, float* __restrict__ C1, float* __restrict__ C2,
    int nb1, int nb2, int ld0, int ld1, int ld2, int M, int N, int K) {
    extern __shared__ char gsm[];
    const uint32_t uBase = smem_u32(gsm);

    const int tid = threadIdx.x, wid = tid >> 5, lane = tid & 31;
    const int m0 = blockIdx.y * 128, n0 = blockIdx.x * 128;
    const int warp_m = (wid >> 2) * 64;
    const int warp_n = (wid & 3) * 32;

    const int a_roff = ((lane >> 3) & 1) * 8 + (lane & 7);
    const int a_coff = (lane >> 4) * 8;
    const int b_roff = (lane >> 4) * 8 + (lane & 7);
    const int b_coff = ((lane >> 3) & 1) * 8;

    float acc[4][4][4];
#pragma unroll
    for (int i = 0; i < 4; i++)
#pragma unroll
        for (int j = 0; j < 4; j++)
#pragma unroll
            for (int c = 0; c < 4; c++) acc[i][j][c] = 0.f;

    const __nv_bfloat16* gAh = Ah + (size_t)m0 * K;
    const __nv_bfloat16* gAl = Al + (size_t)m0 * K;
    const __nv_bfloat16* gBh = Bh + (size_t)n0 * K;
    const __nv_bfloat16* gBl = Bl + (size_t)n0 * K;

    const int KC = K >> 5;
    GLOAD(0, 0);
    cp_commit();

    for (int kc = 0; kc < KC; kc++) {
        if (kc + 1 < KC) {
            GLOAD(kc + 1, (kc + 1) & 1);
            cp_commit();
            cp_wait<1>();
        } else {
            cp_wait<0>();
        }
        __syncthreads();

        const uint32_t uS = uBase + (kc & 1) * GSTAGE_B;
        const uint32_t uAh = uS, uAl = uS + GARR;
        const uint32_t uBh = uS + 2 * GARR, uBl = uS + 3 * GARR;

#pragma unroll
        for (int ks = 0; ks < 2; ks++) {
            uint32_t ah[4][4], al[4][4], bh[2][4], bl[2][4];
#pragma unroll
            for (int mt = 0; mt < 4; mt++) {
                uint32_t off =
                    (uint32_t)((warp_m + mt * 16 + a_roff) * GROW +
                               ks * 16 + a_coff) * 2;
                ldsm_x4(ah[mt], uAh + off);
                ldsm_x4(al[mt], uAl + off);
            }
#pragma unroll
            for (int p = 0; p < 2; p++) {
                uint32_t off =
                    (uint32_t)((warp_n + p * 16 + b_roff) * GROW +
                               ks * 16 + b_coff) * 2;
                ldsm_x4(bh[p], uBh + off);
                ldsm_x4(bl[p], uBl + off);
            }
#pragma unroll
            for (int mt = 0; mt < 4; mt++) {
#pragma unroll
                for (int p = 0; p < 2; p++) {
#pragma unroll
                    for (int hf = 0; hf < 2; hf++) {
                        float* c = acc[mt][p * 2 + hf];
                        uint32_t b0h = bh[p][hf * 2], b1h = bh[p][hf * 2 + 1];
                        uint32_t b0l = bl[p][hf * 2], b1l = bl[p][hf * 2 + 1];
                        mma16816(c, ah[mt], b0h, b1h);
                        mma16816(c, ah[mt], b0l, b1l);
                        mma16816(c, al[mt], b0h, b1h);
                    }
                }
            }
        }
        __syncthreads();
    }

    // Epilogue with column routing (QKV fusion)
    float* Cb;
    int ldc, coff;
    if (n0 < nb1) { Cb = C0; ldc = ld0; coff = 0; }
    else if (n0 < nb2) { Cb = C1; ldc = ld1; coff = nb1; }
    else { Cb = C2; ldc = ld2; coff = nb2; }

    const int cr = lane >> 2, cc = (lane & 3) * 2;
#pragma unroll
    for (int mt = 0; mt < 4; mt++) {
#pragma unroll
        for (int nt = 0; nt < 4; nt++) {
            int row = m0 + warp_m + mt * 16 + cr;
            int col = n0 + warp_n + nt * 8 + cc - coff;
            float* c = acc[mt][nt];
            *(float2*)(Cb + (size_t)row * ldc + col) = make_float2(c[0], c[1]);
            *(float2*)(Cb + (size_t)(row + 8) * ldc + col) = make_float2(c[2], c[3]);
        }
    }
}

// ---------------------------------------------------------------------------
// Flash attention on HMMA (causal, GQA, 3-pass hi/lo split)
// BQ=128 (8 warps x 16 rows), BK=64, HD=128. P in registers.
// V row-major + ldmatrix.trans. cp.async double-buffered K/V stages.
// smem bytes: Qh 34816 | Ql 34816 | stage0 {Kh,Kl,Vh,Vl} 69632 | stage1 69632
// ---------------------------------------------------------------------------
#define FROW 136
#define FQ_B (128 * FROW * 2)    // 34816
#define FKV_B (64 * FROW * 2)    // 17408
#define FSTAGE_B (4 * FKV_B)     // 69632
#define FLA_SMEM (2 * FQ_B + 2 * FSTAGE_B)   // 208896

#define KVLOAD(j, st)                                                         \
    do {                                                                      \
        uint32_t uS = uBase + 2 * FQ_B + (st) * FSTAGE_B;                     \
        _Pragma("unroll") for (int t = 0; t < 4; t++) {                       \
            int i = tid + t * 256;                                            \
            int r = i >> 4, c8 = (i & 15) << 3;                               \
            size_t g = ((size_t)(b * SS + (j) * 64 + r) * KVH + kvh) * HD + c8; \
            uint32_t dso = (uint32_t)(r * (FROW * 2) + c8 * 2);               \
            cp16(uS + dso, Kh + g);                                           \
            cp16(uS + FKV_B + dso, Kl + g);                                   \
            cp16(uS + 2 * FKV_B + dso, Vh + g);                               \
            cp16(uS + 3 * FKV_B + dso, Vl + g);                               \
        }                                                                     \
    } while (0)

__global__ __launch_bounds__(256) void flash_mma(
    const __nv_bfloat16* __restrict__ Qh, const __nv_bfloat16* __restrict__ Ql,
    const __nv_bfloat16* __restrict__ Kh, const __nv_bfloat16* __restrict__ Kl,
    const __nv_bfloat16* __restrict__ Vh, const __nv_bfloat16* __restrict__ Vl,
    float* __restrict__ O) {
    extern __shared__ char fsm[];
    const uint32_t uBase = smem_u32(fsm);
    const uint32_t uQh = uBase, uQl = uBase + FQ_B;

    const int qt = gridDim.x - 1 - blockIdx.x;   // heavy tiles first
    const int h = blockIdx.y, b = blockIdx.z;
    const int kvh = h >> 2;
    const int tid = threadIdx.x, wid = tid >> 5, lane = tid & 31;
    const int cr = lane >> 2, tc = (lane & 3) << 1;

    const int a_roff = ((lane >> 3) & 1) * 8 + (lane & 7);
    const int a_coff = (lane >> 4) * 8;
    const int b_roff = (lane >> 4) * 8 + (lane & 7);
    const int b_coff = ((lane >> 3) & 1) * 8;
    // trans-ldmatrix lane mapping for V (row-major [seq][d])
    const int v_roff = ((lane >> 3) & 1) * 8 + (lane & 7);
    const int v_coff = (lane >> 4) * 8;

    // Q tile via cp.async (group 0)
    {
        const size_t qbase = ((size_t)(b * SS + qt * 128) * HH + h) * HD;
#pragma unroll
        for (int t = 0; t < 8; t++) {
            int i = tid + t * 256;
            int r = i >> 4, c8 = (i & 15) << 3;
            size_t g = qbase + (size_t)r * (HH * HD) + c8;
            uint32_t dso = (uint32_t)(r * (FROW * 2) + c8 * 2);
            cp16(uQh + dso, Qh + g);
            cp16(uQl + dso, Ql + g);
        }
        cp_commit();
    }
    // KV tile 0 (group 1)
    KVLOAD(0, 0);
    cp_commit();

    uint32_t qh[8][4];
    float oacc[16][4];
#pragma unroll
    for (int i = 0; i < 16; i++)
#pragma unroll
        for (int c = 0; c < 4; c++) oacc[i][c] = 0.f;
    float m0 = -1e30f, m1 = -1e30f, l0 = 0.f, l1 = 0.f;

    const int border = qt * 128 + wid * 16;
    const int jmax = 2 * qt + 1;

    for (int j = 0; j <= jmax; j++) {
        if (j + 1 <= jmax) {
            KVLOAD(j + 1, (j + 1) & 1);
            cp_commit();
            cp_wait<1>();
        } else {
            cp_wait<0>();
        }
        __syncthreads();

        if (j == 0) {
#pragma unroll
            for (int ks = 0; ks < 8; ks++)
                ldsm_x4(qh[ks],
                        uQh + (uint32_t)((wid * 16 + a_roff) * FROW +
                                         ks * 16 + a_coff) * 2);
        }

        const uint32_t uS = uBase + 2 * FQ_B + (j & 1) * FSTAGE_B;
        const uint32_t uKh = uS, uKl = uS + FKV_B;
        const uint32_t uVh = uS + 2 * FKV_B, uVl = uS + 3 * FKV_B;

        if (j * 64 <= border + 15) {
            // ---- Scores S[16x64] = Q @ K^T (3-pass split) ----
            float sacc[8][4];
#pragma unroll
            for (int nt = 0; nt < 8; nt++)
#pragma unroll
                for (int c = 0; c < 4; c++) sacc[nt][c] = 0.f;

#pragma unroll
            for (int ks = 0; ks < 8; ks++) {
                uint32_t kh4[4][4], kl4[4][4], qlf[4];
#pragma unroll
                for (int p = 0; p < 4; p++) {
                    uint32_t off =
                        (uint32_t)((p * 16 + b_roff) * FROW +
                                   ks * 16 + b_coff) * 2;
                    ldsm_x4(kh4[p], uKh + off);
                    ldsm_x4(kl4[p], uKl + off);
                }
                ldsm_x4(qlf, uQl + (uint32_t)((wid * 16 + a_roff) * FROW +
                                              ks * 16 + a_coff) * 2);
#pragma unroll
                for (int p = 0; p < 4; p++)
#pragma unroll
                    for (int hf = 0; hf < 2; hf++) {
                        float* c = sacc[p * 2 + hf];
                        mma16816(c, qh[ks], kh4[p][hf * 2], kh4[p][hf * 2 + 1]);
                        mma16816(c, qh[ks], kl4[p][hf * 2], kl4[p][hf * 2 + 1]);
                        mma16816(c, qlf,    kh4[p][hf * 2], kh4[p][hf * 2 + 1]);
                    }
            }

            // ---- Causal mask (diagonal tiles only) ----
            if (j * 64 + 63 > border) {
                int qg0 = border + cr, qg1 = qg0 + 8;
#pragma unroll
                for (int nt = 0; nt < 8; nt++) {
                    int kg = j * 64 + nt * 8 + tc;
                    if (kg > qg0) sacc[nt][0] = -1e30f;
                    if (kg + 1 > qg0) sacc[nt][1] = -1e30f;
                    if (kg > qg1) sacc[nt][2] = -1e30f;
                    if (kg + 1 > qg1) sacc[nt][3] = -1e30f;
                }
            }

            // ---- Online softmax ----
            float mx0 = -1e30f, mx1 = -1e30f;
#pragma unroll
            for (int nt = 0; nt < 8; nt++) {
                mx0 = fmaxf(mx0, fmaxf(sacc[nt][0], sacc[nt][1]));
                mx1 = fmaxf(mx1, fmaxf(sacc[nt][2], sacc[nt][3]));
            }
            mx0 = fmaxf(mx0, __shfl_xor_sync(0xffffffffu, mx0, 1, 4));
            mx0 = fmaxf(mx0, __shfl_xor_sync(0xffffffffu, mx0, 2, 4));
            mx1 = fmaxf(mx1, __shfl_xor_sync(0xffffffffu, mx1, 1, 4));
            mx1 = fmaxf(mx1, __shfl_xor_sync(0xffffffffu, mx1, 2, 4));
            float mn0 = fmaxf(m0, mx0), mn1 = fmaxf(m1, mx1);
            float al0 = __expf(m0 - mn0), al1 = __expf(m1 - mn1);

            float sum0 = 0.f, sum1 = 0.f;
            uint32_t ph[8][2], pl[8][2];
#pragma unroll
            for (int nt = 0; nt < 8; nt++) {
                float p00 = __expf(sacc[nt][0] - mn0);
                float p01 = __expf(sacc[nt][1] - mn0);
                float p10 = __expf(sacc[nt][2] - mn1);
                float p11 = __expf(sacc[nt][3] - mn1);
                sum0 += p00 + p01;
                sum1 += p10 + p11;
                __nv_bfloat16 h0 = __float2bfloat16(p00), h1 = __float2bfloat16(p01);
                __nv_bfloat16 h2 = __float2bfloat16(p10), h3 = __float2bfloat16(p11);
                ph[nt][0] = pack_bf16(h0, h1);
                ph[nt][1] = pack_bf16(h2, h3);
                pl[nt][0] = pack_bf16(__float2bfloat16(p00 - __bfloat162float(h0)),
                                      __float2bfloat16(p01 - __bfloat162float(h1)));
                pl[nt][1] = pack_bf16(__float2bfloat16(p10 - __bfloat162float(h2)),
                                      __float2bfloat16(p11 - __bfloat162float(h3)));
            }
            sum0 += __shfl_xor_sync(0xffffffffu, sum0, 1, 4);
            sum0 += __shfl_xor_sync(0xffffffffu, sum0, 2, 4);
            sum1 += __shfl_xor_sync(0xffffffffu, sum1, 1, 4);
            sum1 += __shfl_xor_sync(0xffffffffu, sum1, 2, 4);
            l0 = l0 * al0 + sum0;
            l1 = l1 * al1 + sum1;
            m0 = mn0;
            m1 = mn1;
#pragma unroll
            for (int nt = 0; nt < 16; nt++) {
                oacc[nt][0] *= al0;
                oacc[nt][1] *= al0;
                oacc[nt][2] *= al1;
                oacc[nt][3] *= al1;
            }

            // ---- O += P @ V (3-pass split; V via ldmatrix.trans) ----
#pragma unroll
            for (int ks = 0; ks < 4; ks++) {
                uint32_t ah4[4] = {ph[2 * ks][0], ph[2 * ks][1],
                                   ph[2 * ks + 1][0], ph[2 * ks + 1][1]};
                uint32_t alo[4] = {pl[2 * ks][0], pl[2 * ks][1],
                                   pl[2 * ks + 1][0], pl[2 * ks + 1][1]};
#pragma unroll
                for (int p = 0; p < 8; p++) {
                    uint32_t vh4[4], vl4[4];
                    uint32_t off =
                        (uint32_t)((ks * 16 + v_roff) * FROW +
                                   p * 16 + v_coff) * 2;
                    ldsm_x4_t(vh4, uVh + off);
                    ldsm_x4_t(vl4, uVl + off);
#pragma unroll
                    for (int hf = 0; hf < 2; hf++) {
                        float* c = oacc[p * 2 + hf];
                        mma16816(c, ah4, vh4[hf * 2], vh4[hf * 2 + 1]);
                        mma16816(c, ah4, vl4[hf * 2], vl4[hf * 2 + 1]);
                        mma16816(c, alo, vh4[hf * 2], vh4[hf * 2 + 1]);
                    }
                }
            }
        }
        __syncthreads();
    }

    // ---- Epilogue ----
    float inv0 = 1.0f / l0, inv1 = 1.0f / l1;
    int row0 = qt * 128 + wid * 16 + cr;
    float* Ob = O + ((size_t)(b * SS + row0) * HH + h) * HD;
#pragma unroll
    for (int nt = 0; nt < 16; nt++) {
        int col = nt * 8 + tc;
        *(float2*)(Ob + col) =
            make_float2(oacc[nt][0] * inv0, oacc[nt][1] * inv0);
        *(float2*)(Ob + (size_t)8 * (HH * HD) + col) =
            make_float2(oacc[nt][2] * inv1, oacc[nt][3] * inv1);
    }
}

// ---------------------------------------------------------------------------
// Launch
// ---------------------------------------------------------------------------
extern "C" void kernel_launch(void* const* d_in, const int* in_sizes, int n_in,
                              void* d_out, int out_size) {
    const float* x  = (const float*)d_in[0];
    const float* Wq = (const float*)d_in[1];
    const float* Wk = (const float*)d_in[2];
    const float* Wv = (const float*)d_in[3];
    const float* Wo = (const float*)d_in[4];

    float *Q, *K, *V, *CTX;
    cudaGetSymbolAddress((void**)&Q, g_Q);
    cudaGetSymbolAddress((void**)&K, g_K);
    cudaGetSymbolAddress((void**)&V, g_V);
    cudaGetSymbolAddress((void**)&CTX, g_CTX);
    __nv_bfloat16 *Xh, *Xl, *CXh, *CXl, *Wch, *Wcl, *Woh, *Wol,
        *Kbh, *Kbl, *Vbh, *Vbl;
    cudaGetSymbolAddress((void**)&Xh, g_Xh);
    cudaGetSymbolAddress((void**)&Xl, g_Xl);
    cudaGetSymbolAddress((void**)&CXh, g_CXh);
    cudaGetSymbolAddress((void**)&CXl, g_CXl);
    cudaGetSymbolAddress((void**)&Wch, g_Wch);
    cudaGetSymbolAddress((void**)&Wcl, g_Wcl);
    cudaGetSymbolAddress((void**)&Woh, g_Woh);
    cudaGetSymbolAddress((void**)&Wol, g_Wol);
    cudaGetSymbolAddress((void**)&Kbh, g_Kbh);
    cudaGetSymbolAddress((void**)&Kbl, g_Kbl);
    cudaGetSymbolAddress((void**)&Vbh, g_Vbh);
    cudaGetSymbolAddress((void**)&Vbl, g_Vbl);

    cudaFuncSetAttribute(gemm_mma, cudaFuncAttributeMaxDynamicSharedMemorySize,
                         GEMM_SMEM);
    cudaFuncSetAttribute(flash_mma, cudaFuncAttributeMaxDynamicSharedMemorySize,
                         FLA_SMEM);

    // Split x; transpose+split weights (QKV weights into one concat buffer)
    split_kernel<<<(ROWS * EE / 4 + 255) / 256, 256>>>(x, Xh, Xl, ROWS * EE / 4);
    tsplit_kernel<<<dim3(EE / 32, EE / 32), 256>>>(Wq, Wch, Wcl, EE, EE);
    tsplit_kernel<<<dim3((KVH * HD) / 32, EE / 32), 256>>>(
        Wk, Wch + (size_t)EE * EE, Wcl + (size_t)EE * EE, EE, KVH * HD);
    tsplit_kernel<<<dim3((KVH * HD) / 32, EE / 32), 256>>>(
        Wv, Wch + (size_t)(EE + KVH * HD) * EE, Wcl + (size_t)(EE + KVH * HD) * EE,
        EE, KVH * HD);
    tsplit_kernel<<<dim3(EE / 32, EE / 32), 256>>>(Wo, Woh, Wol, EE, EE);

    // Fused QKV projection (one launch, 768 CTAs)
    const int NC = EE + 2 * KVH * HD;  // 3072
    gemm_mma<<<dim3(NC / 128, ROWS / 128), 256, GEMM_SMEM>>>(
        Xh, Xl, Wch, Wcl, Q, K, V, EE, EE + KVH * HD,
        HH * HD, KVH * HD, KVH * HD, ROWS, NC, EE);

    // RoPE + scale + bf16 split
    const float scale = 0.08838834764831845f;  // 1/sqrt(HD)
    rope_split_kernel<<<(ROWS * HH * 32 + 255) / 256, 256>>>(
        Q, Xh, Xl, HH, scale, ROWS * HH * 32);
    rope_split_kernel<<<(ROWS * KVH * 32 + 255) / 256, 256>>>(
        K, Kbh, Kbl, KVH, 1.0f, ROWS * KVH * 32);
    split_kernel<<<(ROWS * KVH * HD / 4 + 255) / 256, 256>>>(
        V, Vbh, Vbl, ROWS * KVH * HD / 4);

    // Flash attention on tensor cores
    flash_mma<<<dim3(SS / 128, HH, BB), 256, FLA_SMEM>>>(
        Xh, Xl, Kbh, Kbl, Vbh, Vbl, CTX);

    // Output projection
    split_kernel<<<(ROWS * EE / 4 + 255) / 256, 256>>>(CTX, CXh, CXl, ROWS * EE / 4);
    gemm_mma<<<dim3(EE / 128, ROWS / 128), 256, GEMM_SMEM>>>(
        CXh, CXl, Woh, Wol, (float*)d_out, nullptr, nullptr, EE, EE,
        EE, EE, EE, ROWS, EE, EE);
}

// round 7
// speedup vs baseline: 3.3895x; 1.0043x over previous
#include <cuda_runtime.h>
#include <cuda_bf16.h>
#include <math.h>
#include <stdint.h>

// Problem dims
#define BB 2
#define SS 2048
#define EE 2048
#define HH 16
#define KVH 4
#define HD 128
#define ROWS (BB * SS)    // 4096
#define NKV (KVH * HD)    // 512
#define NC (EE + 2 * NKV) // 3072

// ---------------------------------------------------------------------------
// Scratch (__device__ globals; no cudaMalloc allowed)
// ---------------------------------------------------------------------------
__device__ __nv_bfloat16 g_Xh[(size_t)ROWS * EE];
__device__ __nv_bfloat16 g_Xl[(size_t)ROWS * EE];
__device__ __nv_bfloat16 g_Qbh[(size_t)ROWS * EE];
__device__ __nv_bfloat16 g_Qbl[(size_t)ROWS * EE];
__device__ __nv_bfloat16 g_Kbh[(size_t)ROWS * NKV];
__device__ __nv_bfloat16 g_Kbl[(size_t)ROWS * NKV];
__device__ __nv_bfloat16 g_Vbh[(size_t)ROWS * NKV];
__device__ __nv_bfloat16 g_Vbl[(size_t)ROWS * NKV];
__device__ __nv_bfloat16 g_CXh[(size_t)ROWS * EE];
__device__ __nv_bfloat16 g_CXl[(size_t)ROWS * EE];
__device__ __nv_bfloat16 g_Wch[(size_t)NC * EE];
__device__ __nv_bfloat16 g_Wcl[(size_t)NC * EE];
__device__ __nv_bfloat16 g_Woh[(size_t)EE * EE];
__device__ __nv_bfloat16 g_Wol[(size_t)EE * EE];

// ---------------------------------------------------------------------------
// MMA / cp.async helpers
// ---------------------------------------------------------------------------
__device__ __forceinline__ uint32_t smem_u32(const void* p) {
    uint32_t a;
    asm("{ .reg .u64 t; cvta.to.shared.u64 t, %1; cvt.u32.u64 %0, t; }"
        : "=r"(a) : "l"(p));
    return a;
}
__device__ __forceinline__ void ldsm_x4(uint32_t* r, uint32_t addr) {
    asm volatile("ldmatrix.sync.aligned.m8n8.x4.shared.b16 {%0,%1,%2,%3}, [%4];"
                 : "=r"(r[0]), "=r"(r[1]), "=r"(r[2]), "=r"(r[3]) : "r"(addr));
}
__device__ __forceinline__ void ldsm_x4_t(uint32_t* r, uint32_t addr) {
    asm volatile("ldmatrix.sync.aligned.m8n8.x4.trans.shared.b16 {%0,%1,%2,%3}, [%4];"
                 : "=r"(r[0]), "=r"(r[1]), "=r"(r[2]), "=r"(r[3]) : "r"(addr));
}
__device__ __forceinline__ void mma16816(float* c, const uint32_t* a,
                                         uint32_t b0, uint32_t b1) {
    asm volatile(
        "mma.sync.aligned.m16n8k16.row.col.f32.bf16.bf16.f32 "
        "{%0,%1,%2,%3}, {%4,%5,%6,%7}, {%8,%9}, {%0,%1,%2,%3};"
        : "+f"(c[0]), "+f"(c[1]), "+f"(c[2]), "+f"(c[3])
        : "r"(a[0]), "r"(a[1]), "r"(a[2]), "r"(a[3]), "r"(b0), "r"(b1));
}
__device__ __forceinline__ void cp16(uint32_t dst, const void* src) {
    asm volatile("cp.async.cg.shared.global [%0], [%1], 16;" :: "r"(dst), "l"(src));
}
__device__ __forceinline__ void cp_commit() {
    asm volatile("cp.async.commit_group;" ::: "memory");
}
template <int N> __device__ __forceinline__ void cp_wait() {
    asm volatile("cp.async.wait_group %0;" :: "n"(N) : "memory");
}
__device__ __forceinline__ uint32_t pack_bf16(__nv_bfloat16 a, __nv_bfloat16 b) {
    __nv_bfloat162 t(a, b);
    return *(uint32_t*)&t;
}
// split-write a fp32 pair to hi/lo bf16 buffers (offset must be even)
__device__ __forceinline__ void wsplit(__nv_bfloat16* __restrict__ H,
                                       __nv_bfloat16* __restrict__ L,
                                       size_t o, float a, float b) {
    __nv_bfloat16 h0 = __float2bfloat16(a), h1 = __float2bfloat16(b);
    *(uint32_t*)(H + o) = pack_bf16(h0, h1);
    *(uint32_t*)(L + o) =
        pack_bf16(__float2bfloat16(a - __bfloat162float(h0)),
                  __float2bfloat16(b - __bfloat162float(h1)));
}

// ---------------------------------------------------------------------------
// fp32 -> (hi, lo) bf16 split, elementwise (vectorized x4)
// ---------------------------------------------------------------------------
__global__ __launch_bounds__(256) void split_kernel(const float* __restrict__ in,
                                                    __nv_bfloat16* __restrict__ hi,
                                                    __nv_bfloat16* __restrict__ lo,
                                                    int n4) {
    int i = blockIdx.x * blockDim.x + threadIdx.x;
    if (i >= n4) return;
    float4 v = ((const float4*)in)[i];
    __nv_bfloat16 h0 = __float2bfloat16(v.x), h1 = __float2bfloat16(v.y);
    __nv_bfloat16 h2 = __float2bfloat16(v.z), h3 = __float2bfloat16(v.w);
    __nv_bfloat16 l0 = __float2bfloat16(v.x - __bfloat162float(h0));
    __nv_bfloat16 l1 = __float2bfloat16(v.y - __bfloat162float(h1));
    __nv_bfloat16 l2 = __float2bfloat16(v.z - __bfloat162float(h2));
    __nv_bfloat16 l3 = __float2bfloat16(v.w - __bfloat162float(h3));
    ((__nv_bfloat162*)hi)[i * 2 + 0] = __nv_bfloat162(h0, h1);
    ((__nv_bfloat162*)hi)[i * 2 + 1] = __nv_bfloat162(h2, h3);
    ((__nv_bfloat162*)lo)[i * 2 + 0] = __nv_bfloat162(l0, l1);
    ((__nv_bfloat162*)lo)[i * 2 + 1] = __nv_bfloat162(l2, l3);
}

// ---------------------------------------------------------------------------
// Transpose + split: in fp32 [Kd, Nd] -> out bf16 [Nd, Kd] (hi, lo)
// ---------------------------------------------------------------------------
__global__ __launch_bounds__(256) void tsplit_kernel(const float* __restrict__ in,
                                                     __nv_bfloat16* __restrict__ oh,
                                                     __nv_bfloat16* __restrict__ ol,
                                                     int Kd, int Nd) {
    __shared__ float t[32][33];
    int n0 = blockIdx.x * 32, k0 = blockIdx.y * 32;
    int tx = threadIdx.x & 31, ty = threadIdx.x >> 5;
#pragma unroll
    for (int j = 0; j < 4; j++)
        t[ty + j * 8][tx] = in[(size_t)(k0 + ty + j * 8) * Nd + n0 + tx];
    __syncthreads();
#pragma unroll
    for (int j = 0; j < 4; j++) {
        float v = t[tx][ty + j * 8];
        __nv_bfloat16 h = __float2bfloat16(v);
        __nv_bfloat16 l = __float2bfloat16(v - __bfloat162float(h));
        size_t o = (size_t)(n0 + ty + j * 8) * Kd + k0 + tx;
        oh[o] = h;
        ol[o] = l;
    }
}

// ---------------------------------------------------------------------------
// HMMA bf16 split-precision GEMM with cp.async double buffering.
// mode 0: plain fp32 C write (Cf).
// mode 1: QKV fused epilogue — RoPE+scale+split for Q cols [0,2048),
//         RoPE+split for K cols [2048,2560), split for V cols [2560,3072).
// ---------------------------------------------------------------------------
#define GROW 40
#define GARR (128 * GROW * 2)
#define GSTAGE_B (4 * GARR)
#define GEMM_SMEM (2 * GSTAGE_B)

#define GLOAD(kc, st)                                                        \
    do {                                                                     \
        uint32_t uS = uBase + (st) * GSTAGE_B;                               \
        int koff = (kc) * 32;                                                \
        _Pragma("unroll") for (int t = 0; t < 2; t++) {                      \
            int idx = tid + t * 256;                                         \
            int r = idx >> 2, c8 = (idx & 3) * 8;                            \
            size_t go = (size_t)r * K + koff + c8;                           \
            uint32_t dso = (uint32_t)(r * (GROW * 2) + c8 * 2);              \
            cp16(uS + dso, gAh + go);                                        \
            cp16(uS + GARR + dso, gAl + go);                                 \
            cp16(uS + 2 * GARR + dso, gBh + go);                             \
            cp16(uS + 3 * GARR + dso, gBl + go);                             \
        }                                                                    \
    } while (0)

__global__ __launch_bounds__(256, 2) void gemm_mma(
    const __nv_bfloat16* __restrict__ Ah, const __nv_bfloat16* __restrict__ Al,
    const __nv_bfloat16* __restrict__ Bh, const __nv_bfloat16* __restrict__ Bl,
    float* __restrict__ Cf,
    __nv_bfloat16* __restrict__ Qh, __nv_bfloat16* __restrict__ Ql,
    __nv_bfloat16* __restrict__ Kh2, __nv_bfloat16* __restrict__ Kl2,
    __nv_bfloat16* __restrict__ Vh2, __nv_bfloat16* __restrict__ Vl2,
    int mode, int M, int N, int K) {
    extern __shared__ char gsm[];
    const uint32_t uBase = smem_u32(gsm);

    const int tid = threadIdx.x, wid = tid >> 5, lane = tid & 31;
    const int m0 = blockIdx.y * 128, n0 = blockIdx.x * 128;
    const int warp_m = (wid >> 2) * 64;
    const int warp_n = (wid & 3) * 32;

    const int a_roff = ((lane >> 3) & 1) * 8 + (lane & 7);
    const int a_coff = (lane >> 4) * 8;
    const int b_roff = (lane >> 4) * 8 + (lane & 7);
    const int b_coff = ((lane >> 3) & 1) * 8;

    float acc[4][4][4];
#pragma unroll
    for (int i = 0; i < 4; i++)
#pragma unroll
        for (int j = 0; j < 4; j++)
#pragma unroll
            for (int c = 0; c < 4; c++) acc[i][j][c] = 0.f;

    const __nv_bfloat16* gAh = Ah + (size_t)m0 * K;
    const __nv_bfloat16* gAl = Al + (size_t)m0 * K;
    const __nv_bfloat16* gBh = Bh + (size_t)n0 * K;
    const __nv_bfloat16* gBl = Bl + (size_t)n0 * K;

    const int KC = K >> 5;
    GLOAD(0, 0);
    cp_commit();

    for (int kc = 0; kc < KC; kc++) {
        if (kc + 1 < KC) {
            GLOAD(kc + 1, (kc + 1) & 1);
            cp_commit();
            cp_wait<1>();
        } else {
            cp_wait<0>();
        }
        __syncthreads();

        const uint32_t uS = uBase + (kc & 1) * GSTAGE_B;
        const uint32_t uAh = uS, uAl = uS + GARR;
        const uint32_t uBh = uS + 2 * GARR, uBl = uS + 3 * GARR;

#pragma unroll
        for (int ks = 0; ks < 2; ks++) {
            uint32_t ah[4][4], al[4][4], bh[2][4], bl[2][4];
#pragma unroll
            for (int mt = 0; mt < 4; mt++) {
                uint32_t off =
                    (uint32_t)((warp_m + mt * 16 + a_roff) * GROW +
                               ks * 16 + a_coff) * 2;
                ldsm_x4(ah[mt], uAh + off);
                ldsm_x4(al[mt], uAl + off);
            }
#pragma unroll
            for (int p = 0; p < 2; p++) {
                uint32_t off =
                    (uint32_t)((warp_n + p * 16 + b_roff) * GROW +
                               ks * 16 + b_coff) * 2;
                ldsm_x4(bh[p], uBh + off);
                ldsm_x4(bl[p], uBl + off);
            }
#pragma unroll
            for (int mt = 0; mt < 4; mt++) {
#pragma unroll
                for (int p = 0; p < 2; p++) {
#pragma unroll
                    for (int hf = 0; hf < 2; hf++) {
                        float* c = acc[mt][p * 2 + hf];
                        uint32_t b0h = bh[p][hf * 2], b1h = bh[p][hf * 2 + 1];
                        uint32_t b0l = bl[p][hf * 2], b1l = bl[p][hf * 2 + 1];
                        mma16816(c, ah[mt], b0h, b1h);
                        mma16816(c, ah[mt], b0l, b1l);
                        mma16816(c, al[mt], b0h, b1h);
                    }
                }
            }
        }
        __syncthreads();
    }

    const int cr = lane >> 2, cc = (lane & 3) * 2;
    if (mode == 0) {
        // plain fp32 epilogue
#pragma unroll
        for (int mt = 0; mt < 4; mt++) {
#pragma unroll
            for (int nt = 0; nt < 4; nt++) {
                int row = m0 + warp_m + mt * 16 + cr;
                int col = n0 + warp_n + nt * 8 + cc;
                float* c = acc[mt][nt];
                *(float2*)(Cf + (size_t)row * N + col) = make_float2(c[0], c[1]);
                *(float2*)(Cf + (size_t)(row + 8) * N + col) =
                    make_float2(c[2], c[3]);
            }
        }
    } else {
        // QKV fused epilogue: col pair (col, col+1) is a RoPE rotation pair
        const float qscale = 0.08838834764831845f;  // 1/sqrt(HD)
#pragma unroll
        for (int mt = 0; mt < 4; mt++) {
#pragma unroll
            for (int nt = 0; nt < 4; nt++) {
                int row = m0 + warp_m + mt * 16 + cr;
                int col = n0 + warp_n + nt * 8 + cc;
                float* c = acc[mt][nt];
                int s0 = row & (SS - 1);
                if (col < EE) {
                    // Q: rope + scale
                    int i = (col & (HD - 1)) >> 1;
                    float f = exp2f(-(float)i * (13.287712379549449f / 64.0f));
                    float sn0, cs0, sn1, cs1;
                    sincosf((float)s0 * f, &sn0, &cs0);
                    sincosf((float)(s0 + 8) * f, &sn1, &cs1);
                    wsplit(Qh, Ql, (size_t)row * EE + col,
                           (c[0] * cs0 - c[1] * sn0) * qscale,
                           (c[0] * sn0 + c[1] * cs0) * qscale);
                    wsplit(Qh, Ql, (size_t)(row + 8) * EE + col,
                           (c[2] * cs1 - c[3] * sn1) * qscale,
                           (c[2] * sn1 + c[3] * cs1) * qscale);
                } else if (col < EE + NKV) {
                    // K: rope only
                    int colk = col - EE;
                    int i = (colk & (HD - 1)) >> 1;
                    float f = exp2f(-(float)i * (13.287712379549449f / 64.0f));
                    float sn0, cs0, sn1, cs1;
                    sincosf((float)s0 * f, &sn0, &cs0);
                    sincosf((float)(s0 + 8) * f, &sn1, &cs1);
                    wsplit(Kh2, Kl2, (size_t)row * NKV + colk,
                           c[0] * cs0 - c[1] * sn0, c[0] * sn0 + c[1] * cs0);
                    wsplit(Kh2, Kl2, (size_t)(row + 8) * NKV + colk,
                           c[2] * cs1 - c[3] * sn1, c[2] * sn1 + c[3] * cs1);
                } else {
                    // V: split only
                    int colv = col - EE - NKV;
                    wsplit(Vh2, Vl2, (size_t)row * NKV + colv, c[0], c[1]);
                    wsplit(Vh2, Vl2, (size_t)(row + 8) * NKV + colv, c[2], c[3]);
                }
            }
        }
    }
}

// ---------------------------------------------------------------------------
// Flash attention on HMMA (causal, GQA, 3-pass hi/lo split)
// BQ=128 (8 warps x 16 rows), BK=64, HD=128. P in registers.
// Epilogue writes bf16 hi/lo context directly (fused split).
// ---------------------------------------------------------------------------
#define FROW 136
#define FQ_B (128 * FROW * 2)
#define FKV_B (64 * FROW * 2)
#define FSTAGE_B (4 * FKV_B)
#define FLA_SMEM (2 * FQ_B + 2 * FSTAGE_B)   // 208896

#define KVLOAD(j, st)                                                         \
    do {                                                                      \
        uint32_t uS = uBase + 2 * FQ_B + (st) * FSTAGE_B;                     \
        _Pragma("unroll") for (int t = 0; t < 4; t++) {                       \
            int i = tid + t * 256;                                            \
            int r = i >> 4, c8 = (i & 15) << 3;                               \
            size_t g = (size_t)(b * SS + (j) * 64 + r) * NKV + kvh * HD + c8; \
            uint32_t dso = (uint32_t)(r * (FROW * 2) + c8 * 2);               \
            cp16(uS + dso, Kh + g);                                           \
            cp16(uS + FKV_B + dso, Kl + g);                                   \
            cp16(uS + 2 * FKV_B + dso, Vh + g);                               \
            cp16(uS + 3 * FKV_B + dso, Vl + g);                               \
        }                                                                     \
    } while (0)

__global__ __launch_bounds__(256) void flash_mma(
    const __nv_bfloat16* __restrict__ Qh, const __nv_bfloat16* __restrict__ Ql,
    const __nv_bfloat16* __restrict__ Kh, const __nv_bfloat16* __restrict__ Kl,
    const __nv_bfloat16* __restrict__ Vh, const __nv_bfloat16* __restrict__ Vl,
    __nv_bfloat16* __restrict__ Oh, __nv_bfloat16* __restrict__ Ol) {
    extern __shared__ char fsm[];
    const uint32_t uBase = smem_u32(fsm);
    const uint32_t uQh = uBase, uQl = uBase + FQ_B;

    const int qt = gridDim.x - 1 - blockIdx.x;   // heavy tiles first
    const int h = blockIdx.y, b = blockIdx.z;
    const int kvh = h >> 2;
    const int tid = threadIdx.x, wid = tid >> 5, lane = tid & 31;
    const int cr = lane >> 2, tc = (lane & 3) << 1;

    const int a_roff = ((lane >> 3) & 1) * 8 + (lane & 7);
    const int a_coff = (lane >> 4) * 8;
    const int b_roff = (lane >> 4) * 8 + (lane & 7);
    const int b_coff = ((lane >> 3) & 1) * 8;
    const int v_roff = ((lane >> 3) & 1) * 8 + (lane & 7);
    const int v_coff = (lane >> 4) * 8;

    {
        const size_t qbase = (size_t)(b * SS + qt * 128) * EE + h * HD;
#pragma unroll
        for (int t = 0; t < 8; t++) {
            int i = tid + t * 256;
            int r = i >> 4, c8 = (i & 15) << 3;
            size_t g = qbase + (size_t)r * EE + c8;
            uint32_t dso = (uint32_t)(r * (FROW * 2) + c8 * 2);
            cp16(uQh + dso, Qh + g);
            cp16(uQl + dso, Ql + g);
        }
        cp_commit();
    }
    KVLOAD(0, 0);
    cp_commit();

    uint32_t qh[8][4];
    float oacc[16][4];
#pragma unroll
    for (int i = 0; i < 16; i++)
#pragma unroll
        for (int c = 0; c < 4; c++) oacc[i][c] = 0.f;
    float m0 = -1e30f, m1 = -1e30f, l0 = 0.f, l1 = 0.f;

    const int border = qt * 128 + wid * 16;
    const int jmax = 2 * qt + 1;

    for (int j = 0; j <= jmax; j++) {
        if (j + 1 <= jmax) {
            KVLOAD(j + 1, (j + 1) & 1);
            cp_commit();
            cp_wait<1>();
        } else {
            cp_wait<0>();
        }
        __syncthreads();

        if (j == 0) {
#pragma unroll
            for (int ks = 0; ks < 8; ks++)
                ldsm_x4(qh[ks],
                        uQh + (uint32_t)((wid * 16 + a_roff) * FROW +
                                         ks * 16 + a_coff) * 2);
        }

        const uint32_t uS = uBase + 2 * FQ_B + (j & 1) * FSTAGE_B;
        const uint32_t uKh = uS, uKl = uS + FKV_B;
        const uint32_t uVh = uS + 2 * FKV_B, uVl = uS + 3 * FKV_B;

        if (j * 64 <= border + 15) {
            float sacc[8][4];
#pragma unroll
            for (int nt = 0; nt < 8; nt++)
#pragma unroll
                for (int c = 0; c < 4; c++) sacc[nt][c] = 0.f;

#pragma unroll
            for (int ks = 0; ks < 8; ks++) {
                uint32_t kh4[4][4], kl4[4][4], qlf[4];
#pragma unroll
                for (int p = 0; p < 4; p++) {
                    uint32_t off =
                        (uint32_t)((p * 16 + b_roff) * FROW +
                                   ks * 16 + b_coff) * 2;
                    ldsm_x4(kh4[p], uKh + off);
                    ldsm_x4(kl4[p], uKl + off);
                }
                ldsm_x4(qlf, uQl + (uint32_t)((wid * 16 + a_roff) * FROW +
                                              ks * 16 + a_coff) * 2);
#pragma unroll
                for (int p = 0; p < 4; p++)
#pragma unroll
                    for (int hf = 0; hf < 2; hf++) {
                        float* c = sacc[p * 2 + hf];
                        mma16816(c, qh[ks], kh4[p][hf * 2], kh4[p][hf * 2 + 1]);
                        mma16816(c, qh[ks], kl4[p][hf * 2], kl4[p][hf * 2 + 1]);
                        mma16816(c, qlf,    kh4[p][hf * 2], kh4[p][hf * 2 + 1]);
                    }
            }

            if (j * 64 + 63 > border) {
                int qg0 = border + cr, qg1 = qg0 + 8;
#pragma unroll
                for (int nt = 0; nt < 8; nt++) {
                    int kg = j * 64 + nt * 8 + tc;
                    if (kg > qg0) sacc[nt][0] = -1e30f;
                    if (kg + 1 > qg0) sacc[nt][1] = -1e30f;
                    if (kg > qg1) sacc[nt][2] = -1e30f;
                    if (kg + 1 > qg1) sacc[nt][3] = -1e30f;
                }
            }

            float mx0 = -1e30f, mx1 = -1e30f;
#pragma unroll
            for (int nt = 0; nt < 8; nt++) {
                mx0 = fmaxf(mx0, fmaxf(sacc[nt][0], sacc[nt][1]));
                mx1 = fmaxf(mx1, fmaxf(sacc[nt][2], sacc[nt][3]));
            }
            mx0 = fmaxf(mx0, __shfl_xor_sync(0xffffffffu, mx0, 1, 4));
            mx0 = fmaxf(mx0, __shfl_xor_sync(0xffffffffu, mx0, 2, 4));
            mx1 = fmaxf(mx1, __shfl_xor_sync(0xffffffffu, mx1, 1, 4));
            mx1 = fmaxf(mx1, __shfl_xor_sync(0xffffffffu, mx1, 2, 4));
            float mn0 = fmaxf(m0, mx0), mn1 = fmaxf(m1, mx1);
            float al0 = __expf(m0 - mn0), al1 = __expf(m1 - mn1);

            float sum0 = 0.f, sum1 = 0.f;
            uint32_t ph[8][2], pl[8][2];
#pragma unroll
            for (int nt = 0; nt < 8; nt++) {
                float p00 = __expf(sacc[nt][0] - mn0);
                float p01 = __expf(sacc[nt][1] - mn0);
                float p10 = __expf(sacc[nt][2] - mn1);
                float p11 = __expf(sacc[nt][3] - mn1);
                sum0 += p00 + p01;
                sum1 += p10 + p11;
                __nv_bfloat16 h0 = __float2bfloat16(p00), h1 = __float2bfloat16(p01);
                __nv_bfloat16 h2 = __float2bfloat16(p10), h3 = __float2bfloat16(p11);
                ph[nt][0] = pack_bf16(h0, h1);
                ph[nt][1] = pack_bf16(h2, h3);
                pl[nt][0] = pack_bf16(__float2bfloat16(p00 - __bfloat162float(h0)),
                                      __float2bfloat16(p01 - __bfloat162float(h1)));
                pl[nt][1] = pack_bf16(__float2bfloat16(p10 - __bfloat162float(h2)),
                                      __float2bfloat16(p11 - __bfloat162float(h3)));
            }
            sum0 += __shfl_xor_sync(0xffffffffu, sum0, 1, 4);
            sum0 += __shfl_xor_sync(0xffffffffu, sum0, 2, 4);
            sum1 += __shfl_xor_sync(0xffffffffu, sum1, 1, 4);
            sum1 += __shfl_xor_sync(0xffffffffu, sum1, 2, 4);
            l0 = l0 * al0 + sum0;
            l1 = l1 * al1 + sum1;
            m0 = mn0;
            m1 = mn1;
#pragma unroll
            for (int nt = 0; nt < 16; nt++) {
                oacc[nt][0] *= al0;
                oacc[nt][1] *= al0;
                oacc[nt][2] *= al1;
                oacc[nt][3] *= al1;
            }

#pragma unroll
            for (int ks = 0; ks < 4; ks++) {
                uint32_t ah4[4] = {ph[2 * ks][0], ph[2 * ks][1],
                                   ph[2 * ks + 1][0], ph[2 * ks + 1][1]};
                uint32_t alo[4] = {pl[2 * ks][0], pl[2 * ks][1],
                                   pl[2 * ks + 1][0], pl[2 * ks + 1][1]};
#pragma unroll
                for (int p = 0; p < 8; p++) {
                    uint32_t vh4[4], vl4[4];
                    uint32_t off =
                        (uint32_t)((ks * 16 + v_roff) * FROW +
                                   p * 16 + v_coff) * 2;
                    ldsm_x4_t(vh4, uVh + off);
                    ldsm_x4_t(vl4, uVl + off);
#pragma unroll
                    for (int hf = 0; hf < 2; hf++) {
                        float* c = oacc[p * 2 + hf];
                        mma16816(c, ah4, vh4[hf * 2], vh4[hf * 2 + 1]);
                        mma16816(c, ah4, vl4[hf * 2], vl4[hf * 2 + 1]);
                        mma16816(c, alo, vh4[hf * 2], vh4[hf * 2 + 1]);
                    }
                }
            }
        }
        __syncthreads();
    }

    // ---- Epilogue: normalize + split to bf16 hi/lo context ----
    float inv0 = 1.0f / l0, inv1 = 1.0f / l1;
    int row0 = qt * 128 + wid * 16 + cr;
    size_t obase = (size_t)(b * SS + row0) * EE + h * HD;
#pragma unroll
    for (int nt = 0; nt < 16; nt++) {
        int col = nt * 8 + tc;
        wsplit(Oh, Ol, obase + col, oacc[nt][0] * inv0, oacc[nt][1] * inv0);
        wsplit(Oh, Ol, obase + (size_t)8 * EE + col,
               oacc[nt][2] * inv1, oacc[nt][3] * inv1);
    }
}

// ---------------------------------------------------------------------------
// Launch
// ---------------------------------------------------------------------------
extern "C" void kernel_launch(void* const* d_in, const int* in_sizes, int n_in,
                              void* d_out, int out_size) {
    const float* x  = (const float*)d_in[0];
    const float* Wq = (const float*)d_in[1];
    const float* Wk = (const float*)d_in[2];
    const float* Wv = (const float*)d_in[3];
    const float* Wo = (const float*)d_in[4];

    __nv_bfloat16 *Xh, *Xl, *Qbh, *Qbl, *Kbh, *Kbl, *Vbh, *Vbl, *CXh, *CXl,
        *Wch, *Wcl, *Woh, *Wol;
    cudaGetSymbolAddress((void**)&Xh, g_Xh);
    cudaGetSymbolAddress((void**)&Xl, g_Xl);
    cudaGetSymbolAddress((void**)&Qbh, g_Qbh);
    cudaGetSymbolAddress((void**)&Qbl, g_Qbl);
    cudaGetSymbolAddress((void**)&Kbh, g_Kbh);
    cudaGetSymbolAddress((void**)&Kbl, g_Kbl);
    cudaGetSymbolAddress((void**)&Vbh, g_Vbh);
    cudaGetSymbolAddress((void**)&Vbl, g_Vbl);
    cudaGetSymbolAddress((void**)&CXh, g_CXh);
    cudaGetSymbolAddress((void**)&CXl, g_CXl);
    cudaGetSymbolAddress((void**)&Wch, g_Wch);
    cudaGetSymbolAddress((void**)&Wcl, g_Wcl);
    cudaGetSymbolAddress((void**)&Woh, g_Woh);
    cudaGetSymbolAddress((void**)&Wol, g_Wol);

    cudaFuncSetAttribute(gemm_mma, cudaFuncAttributeMaxDynamicSharedMemorySize,
                         GEMM_SMEM);
    cudaFuncSetAttribute(flash_mma, cudaFuncAttributeMaxDynamicSharedMemorySize,
                         FLA_SMEM);

    // Split x; transpose+split weights (QKV concat + Wo)
    split_kernel<<<(ROWS * EE / 4 + 255) / 256, 256>>>(x, Xh, Xl, ROWS * EE / 4);
    tsplit_kernel<<<dim3(EE / 32, EE / 32), 256>>>(Wq, Wch, Wcl, EE, EE);
    tsplit_kernel<<<dim3(NKV / 32, EE / 32), 256>>>(
        Wk, Wch + (size_t)EE * EE, Wcl + (size_t)EE * EE, EE, NKV);
    tsplit_kernel<<<dim3(NKV / 32, EE / 32), 256>>>(
        Wv, Wch + (size_t)(EE + NKV) * EE, Wcl + (size_t)(EE + NKV) * EE, EE, NKV);
    tsplit_kernel<<<dim3(EE / 32, EE / 32), 256>>>(Wo, Woh, Wol, EE, EE);

    // Fused QKV projection with RoPE+split epilogue
    gemm_mma<<<dim3(NC / 128, ROWS / 128), 256, GEMM_SMEM>>>(
        Xh, Xl, Wch, Wcl, nullptr, Qbh, Qbl, Kbh, Kbl, Vbh, Vbl,
        1, ROWS, NC, EE);

    // Flash attention (epilogue writes bf16 hi/lo context)
    flash_mma<<<dim3(SS / 128, HH, BB), 256, FLA_SMEM>>>(
        Qbh, Qbl, Kbh, Kbl, Vbh, Vbl, CXh, CXl);

    // Output projection -> d_out (fp32)
    gemm_mma<<<dim3(EE / 128, ROWS / 128), 256, GEMM_SMEM>>>(
        CXh, CXl, Woh, Wol, (float*)d_out, nullptr, nullptr, nullptr, nullptr,
        nullptr, nullptr, 0, ROWS, EE, EE);
}